// round 2
// baseline (speedup 1.0000x reference)
#include <cuda_runtime.h>
#include <math.h>

#define BB 128
#define NN 4096
#define MM 64
#define HH 512
#define PR 1584   // stacked head-param rows: 512 Wk + 512 We + 512 Wa + 24 Ws + 8 Wbeta + 8 Wg + 8 Wgam

// ---------------- scratch (device globals; no allocations) ----------------
__device__ float g_x[BB * 512];            // [x | prev_reads] for LSTM
__device__ float g_c[BB * HH];
__device__ float g_hr[BB * 768];           // [h(512) | read0..3 (4*64)]
__device__ float g_Wstk[PR * 512];         // stacked head-param weights
__device__ float g_gp[4 * BB * 2048];      // gates GEMM split-K partials
__device__ float g_pp[2 * BB * PR];        // head-param GEMM partials
__device__ float g_op[2 * BB * 256];       // output GEMM partials
__device__ float g_keyv[8 * BB * MM];
__device__ float g_keynorm[8 * BB];
__device__ float g_ev[8 * BB * MM];
__device__ float g_av[8 * BB * MM];
__device__ float g_beta[8 * BB];
__device__ float g_gv[8 * BB];
__device__ float g_gamma[8 * BB];
__device__ float g_sv[8 * BB * 3];
__device__ float g_simA[BB * NN];
__device__ float g_simB[BB * NN];
__device__ float g_w[8 * BB * NN];         // final head weights (heads 0..6 used)
__device__ float g_readp[4 * BB * 16 * MM];// per-chunk read partials

__device__ __forceinline__ float sigf(float x) { return 1.f / (1.f + __expf(-x)); }
__device__ __forceinline__ float softplusf(float x) {
    return fmaxf(x, 0.f) + log1pf(expf(-fabsf(x)));
}

// ---------------- pack kernels ----------------
__global__ void pack_x_kernel(const float* __restrict__ in_data,
                              const float* __restrict__ prev_reads) {
    int idx = blockIdx.x * blockDim.x + threadIdx.x;
    if (idx >= BB * 512) return;
    int b = idx >> 9, c = idx & 511;
    float v;
    if (c < 256) v = in_data[b * 256 + c];
    else {
        int k = c - 256, i = k >> 6, m = k & 63;
        v = prev_reads[((size_t)i * BB + b) * MM + m];
    }
    g_x[idx] = v;
}

__global__ void pack_w_kernel(const float* __restrict__ Wk, const float* __restrict__ We,
                              const float* __restrict__ Wa, const float* __restrict__ Ws,
                              const float* __restrict__ Wbeta, const float* __restrict__ Wg,
                              const float* __restrict__ Wgam) {
    int idx = blockIdx.x * blockDim.x + threadIdx.x;
    if (idx >= PR * 512) return;
    int r = idx >> 9, k = idx & 511;
    float v;
    if (r < 512)        v = Wk[(size_t)r * 512 + k];
    else if (r < 1024)  v = We[(size_t)(r - 512) * 512 + k];
    else if (r < 1536)  v = Wa[(size_t)(r - 1024) * 512 + k];
    else if (r < 1560)  v = Ws[(size_t)(r - 1536) * 512 + k];
    else if (r < 1568)  v = Wbeta[(size_t)(r - 1560) * 512 + k];
    else if (r < 1576)  v = Wg[(size_t)(r - 1568) * 512 + k];
    else                v = Wgam[(size_t)(r - 1576) * 512 + k];
    g_Wstk[idx] = v;
}

// ---------------- split-K SGEMM: C[b,r] = sum_k A[b,k]*W[r,k] ----------------
// A [128,K] row-major, W [R,K] row-major. Partials into Cp[slot][128][R].
__global__ __launch_bounds__(256) void gemm_tn(
    const float* __restrict__ A, const float* __restrict__ W,
    float* __restrict__ Cp, int R, int K, int kChunk, int slotBase)
{
    __shared__ __align__(16) float As[16][68];
    __shared__ __align__(16) float Bs[16][68];
    const int t = threadIdx.x;
    const int tx = t & 15, ty = t >> 4;
    const int mBase = blockIdx.y * 64;
    const int rBase = blockIdx.x * 64;
    const int kStart = blockIdx.z * kChunk;
    const int slot = slotBase + blockIdx.z;
    const int loadRow = t >> 2;
    const int loadK = (t & 3) * 4;
    const float* Arow = A + (size_t)(mBase + loadRow) * K;
    const bool wv = (rBase + loadRow) < R;
    const float* Wrow = W + (size_t)(wv ? (rBase + loadRow) : 0) * K;
    float acc[4][4] = {};
    for (int k0 = kStart; k0 < kStart + kChunk; k0 += 16) {
        float4 a4 = *reinterpret_cast<const float4*>(Arow + k0 + loadK);
        float4 w4 = *reinterpret_cast<const float4*>(Wrow + k0 + loadK);
        if (!wv) w4 = make_float4(0.f, 0.f, 0.f, 0.f);
        __syncthreads();
        As[loadK + 0][loadRow] = a4.x; As[loadK + 1][loadRow] = a4.y;
        As[loadK + 2][loadRow] = a4.z; As[loadK + 3][loadRow] = a4.w;
        Bs[loadK + 0][loadRow] = w4.x; Bs[loadK + 1][loadRow] = w4.y;
        Bs[loadK + 2][loadRow] = w4.z; Bs[loadK + 3][loadRow] = w4.w;
        __syncthreads();
#pragma unroll
        for (int kk = 0; kk < 16; kk++) {
            float4 av = *reinterpret_cast<const float4*>(&As[kk][ty * 4]);
            float4 wvv = *reinterpret_cast<const float4*>(&Bs[kk][tx * 4]);
            float aa[4] = {av.x, av.y, av.z, av.w};
            float ww[4] = {wvv.x, wvv.y, wvv.z, wvv.w};
#pragma unroll
            for (int i = 0; i < 4; i++)
#pragma unroll
                for (int j = 0; j < 4; j++)
                    acc[i][j] = fmaf(aa[i], ww[j], acc[i][j]);
        }
    }
#pragma unroll
    for (int i = 0; i < 4; i++) {
        int m = mBase + ty * 4 + i;
#pragma unroll
        for (int j = 0; j < 4; j++) {
            int r = rBase + tx * 4 + j;
            if (r < R) Cp[((size_t)slot * BB + m) * R + r] = acc[i][j];
        }
    }
}

// ---------------- LSTM epilogue ----------------
__global__ void lstm_act_kernel(const float* __restrict__ b_ih, const float* __restrict__ b_hh,
                                const float* __restrict__ c_prev) {
    int idx = blockIdx.x * blockDim.x + threadIdx.x;
    if (idx >= BB * 512) return;
    int b = idx >> 9, j = idx & 511;
    float s[4];
#pragma unroll
    for (int q = 0; q < 4; q++) {
        int col = q * 512 + j;
        float v = b_ih[col] + b_hh[col];
#pragma unroll
        for (int sl = 0; sl < 4; sl++)
            v += g_gp[((size_t)sl * BB + b) * 2048 + col];
        s[q] = v;
    }
    float cc = sigf(s[1]) * c_prev[idx] + sigf(s[0]) * tanhf(s[2]);
    float hh = sigf(s[3]) * tanhf(cc);
    g_c[idx] = cc;
    g_hr[(size_t)b * 768 + j] = hh;
}

// ---------------- head-param epilogue ----------------
__global__ void param_act_kernel(const float* __restrict__ bk, const float* __restrict__ be,
                                 const float* __restrict__ ba, const float* __restrict__ bs,
                                 const float* __restrict__ bbeta, const float* __restrict__ bg,
                                 const float* __restrict__ bgam) {
    int head = blockIdx.x, b = blockIdx.y, t = threadIdx.x;  // 64 threads
    size_t base0 = (size_t)b * PR, base1 = (size_t)(BB + b) * PR;
    auto val = [&](int r) { return g_pp[base0 + r] + g_pp[base1 + r]; };
    int hb = head * BB + b;

    float kv = val(head * 64 + t) + bk[head * 64 + t];
    g_keyv[(size_t)hb * 64 + t] = kv;
    // norm over 64 threads (2 warps)
    __shared__ float sh2[2];
    __shared__ float s3sh[3];
    float ns = kv * kv;
#pragma unroll
    for (int off = 16; off >= 1; off >>= 1) ns += __shfl_xor_sync(0xffffffffu, ns, off);
    if ((t & 31) == 0) sh2[t >> 5] = ns;

    g_ev[(size_t)hb * 64 + t] = sigf(val(512 + head * 64 + t) + be[head * 64 + t]);
    g_av[(size_t)hb * 64 + t] = tanhf(val(1024 + head * 64 + t) + ba[head * 64 + t]);
    if (t < 3) s3sh[t] = val(1536 + head * 3 + t) + bs[head * 3 + t];
    __syncthreads();
    if (t == 0) g_keynorm[hb] = sqrtf(sh2[0] + sh2[1]);
    if (t < 3) {
        float m = fmaxf(s3sh[0], fmaxf(s3sh[1], s3sh[2]));
        float d = expf(s3sh[0] - m) + expf(s3sh[1] - m) + expf(s3sh[2] - m);
        g_sv[(size_t)hb * 3 + t] = expf(s3sh[t] - m) / d;
    }
    if (t == 0) {
        g_beta[hb]  = softplusf(val(1560 + head) + bbeta[head]);
        g_gv[hb]    = sigf(val(1568 + head) + bg[head]);
        g_gamma[hb] = 1.f + softplusf(val(1576 + head) + bgam[head]);
    }
}

// ---------------- memory pass kernels ----------------
__device__ __forceinline__ void upd_row(float4& v, float w, const float4& e, const float4& a) {
    v.x = fmaf(w, fmaf(-e.x, v.x, a.x), v.x);
    v.y = fmaf(w, fmaf(-e.y, v.y, a.y), v.y);
    v.z = fmaf(w, fmaf(-e.z, v.z, a.z), v.z);
    v.w = fmaf(w, fmaf(-e.w, v.w, a.w), v.w);
}

// ST=0: sims h0,h1 on S0.
// ST=1: read h0 (S0), upd h1, sims h2,h3 (S1).
// ST=2: upd h1, read h2 (S1), upd h3, sims h4,h5 (S2).
// ST=3: upd h1,h3, read h4 (S2), upd h5, sim h6 (S3).
// ST=4: upd h1,h3,h5, read h6 (S3).
template <int ST>
__global__ __launch_bounds__(256) void pass_kernel(const float* __restrict__ mem) {
    constexpr bool HAS_READ = (ST >= 1);
    constexpr int READ_HEAD = (ST == 1) ? 0 : (ST == 2) ? 2 : (ST == 3) ? 4 : 6;
    constexpr int RIDX = READ_HEAD / 2;
    constexpr bool HAS_POST = (ST >= 1 && ST <= 3);
    constexpr int POST_HEAD = 2 * ST - 1;
    constexpr int NSIM = (ST <= 2) ? 2 : (ST == 3) ? 1 : 0;
    constexpr int SH0 = 2 * ST;

    const int b = blockIdx.y;
    const int lane = threadIdx.x & 31;
    const int warpId = threadIdx.x >> 5;
    const int li = lane & 15;
    const int half = lane >> 4;
    const int m4 = li * 4;

    auto ldvec = [&](const float* base, int head) -> float4 {
        return *reinterpret_cast<const float4*>(base + ((size_t)head * BB + b) * 64 + m4);
    };

    float4 e1, a1, e3, a3, e5, a5, k0v, k1v;
    float kn0 = 0.f, kn1 = 0.f;
    if (ST >= 1) { e1 = ldvec(g_ev, 1); a1 = ldvec(g_av, 1); }
    if (ST >= 2) { e3 = ldvec(g_ev, 3); a3 = ldvec(g_av, 3); }
    if (ST >= 3) { e5 = ldvec(g_ev, 5); a5 = ldvec(g_av, 5); }
    if (NSIM >= 1) { k0v = ldvec(g_keyv, SH0); kn0 = g_keynorm[SH0 * BB + b]; }
    if (NSIM >= 2) { k1v = ldvec(g_keyv, SH0 + 1); kn1 = g_keynorm[(SH0 + 1) * BB + b]; }

    float r0 = 0.f, r1 = 0.f, r2 = 0.f, r3 = 0.f;
    const int nBase = blockIdx.x * 256 + warpId * 32 + half;
    const size_t bn = (size_t)b * NN;

#pragma unroll 4
    for (int i = 0; i < 16; i++) {
        const int n = nBase + 2 * i;
        float4 v = __ldg(reinterpret_cast<const float4*>(mem + (bn + n) * 64 + m4));
        if (ST >= 2) { float w = __ldg(&g_w[((size_t)1 * BB + b) * NN + n]); upd_row(v, w, e1, a1); }
        if (ST >= 3) { float w = __ldg(&g_w[((size_t)3 * BB + b) * NN + n]); upd_row(v, w, e3, a3); }
        if (ST == 4) { float w = __ldg(&g_w[((size_t)5 * BB + b) * NN + n]); upd_row(v, w, e5, a5); }
        if (HAS_READ) {
            float wr = __ldg(&g_w[((size_t)READ_HEAD * BB + b) * NN + n]);
            r0 = fmaf(wr, v.x, r0); r1 = fmaf(wr, v.y, r1);
            r2 = fmaf(wr, v.z, r2); r3 = fmaf(wr, v.w, r3);
        }
        if (HAS_POST) {
            float w = __ldg(&g_w[((size_t)POST_HEAD * BB + b) * NN + n]);
            if (ST == 1) upd_row(v, w, e1, a1);
            else if (ST == 2) upd_row(v, w, e3, a3);
            else upd_row(v, w, e5, a5);
        }
        if (NSIM >= 1) {
            float ns = v.x * v.x + v.y * v.y + v.z * v.z + v.w * v.w;
            float d0 = v.x * k0v.x + v.y * k0v.y + v.z * k0v.z + v.w * k0v.w;
            float d1 = 0.f;
            if (NSIM >= 2) d1 = v.x * k1v.x + v.y * k1v.y + v.z * k1v.z + v.w * k1v.w;
#pragma unroll
            for (int off = 8; off >= 1; off >>= 1) {
                ns += __shfl_xor_sync(0xffffffffu, ns, off);
                d0 += __shfl_xor_sync(0xffffffffu, d0, off);
                if (NSIM >= 2) d1 += __shfl_xor_sync(0xffffffffu, d1, off);
            }
            if (li == 0) {
                float nm = sqrtf(ns);
                g_simA[bn + n] = d0 / (nm * kn0 + 1e-8f);
                if (NSIM >= 2) g_simB[bn + n] = d1 / (nm * kn1 + 1e-8f);
            }
        }
    }

    if (HAS_READ) {
        __shared__ float sred[8][64];
        r0 += __shfl_down_sync(0xffffffffu, r0, 16);
        r1 += __shfl_down_sync(0xffffffffu, r1, 16);
        r2 += __shfl_down_sync(0xffffffffu, r2, 16);
        r3 += __shfl_down_sync(0xffffffffu, r3, 16);
        if (lane < 16) {
            sred[warpId][m4 + 0] = r0; sred[warpId][m4 + 1] = r1;
            sred[warpId][m4 + 2] = r2; sred[warpId][m4 + 3] = r3;
        }
        __syncthreads();
        if (threadIdx.x < 64) {
            float s = 0.f;
#pragma unroll
            for (int w = 0; w < 8; w++) s += sred[w][threadIdx.x];
            g_readp[(((size_t)RIDX * BB + b) * 16 + blockIdx.x) * 64 + threadIdx.x] = s;
        }
    }
}

// ---------------- per-head weight kernel (softmax/interp/shift/sharpen) ----------------
__device__ __forceinline__ float blk_reduce(float v, float* red, bool isMax) {
    int lane = threadIdx.x & 31, wid = threadIdx.x >> 5;
#pragma unroll
    for (int off = 16; off >= 1; off >>= 1) {
        float o = __shfl_xor_sync(0xffffffffu, v, off);
        v = isMax ? fmaxf(v, o) : (v + o);
    }
    if (lane == 0) red[wid] = v;
    __syncthreads();
    if (wid == 0) {
        float x = (lane < 16) ? red[lane] : (isMax ? -1e30f : 0.f);
#pragma unroll
        for (int off = 8; off >= 1; off >>= 1) {
            float o = __shfl_xor_sync(0xffffffffu, x, off);
            x = isMax ? fmaxf(x, o) : (x + o);
        }
        if (lane == 0) red[0] = x;
    }
    __syncthreads();
    float r = red[0];
    __syncthreads();
    return r;
}

__global__ __launch_bounds__(512) void weight_kernel(const float* __restrict__ prev_weights,
                                                     int headBase) {
    __shared__ float sh[NN];
    __shared__ float red[16];
    const int hIdx = blockIdx.x;
    const int head = headBase + hIdx;
    const int b = blockIdx.y;
    const int t = threadIdx.x;
    const int hb = head * BB + b;
    const float* sim = (hIdx == 0 ? g_simA : g_simB) + (size_t)b * NN;
    const float* pw = prev_weights + (size_t)hb * NN;

    const float beta = g_beta[hb], gg = g_gv[hb], gamma = g_gamma[hb];
    const float s0 = g_sv[(size_t)hb * 3 + 0];
    const float s1 = g_sv[(size_t)hb * 3 + 1];
    const float s2 = g_sv[(size_t)hb * 3 + 2];

    float tv[8];
    float mx = -1e30f;
#pragma unroll
    for (int j = 0; j < 8; j++) {
        tv[j] = beta * sim[t + 512 * j];
        mx = fmaxf(mx, tv[j]);
    }
    mx = blk_reduce(mx, red, true);
    float se = 0.f, ev[8];
#pragma unroll
    for (int j = 0; j < 8; j++) { ev[j] = __expf(tv[j] - mx); se += ev[j]; }
    se = blk_reduce(se, red, false);
    const float inv = 1.f / se;
#pragma unroll
    for (int j = 0; j < 8; j++) {
        int n = t + 512 * j;
        sh[n] = gg * (ev[j] * inv) + (1.f - gg) * pw[n];
    }
    __syncthreads();
    float sp = 0.f, wp[8];
#pragma unroll
    for (int j = 0; j < 8; j++) {
        int n = t + 512 * j;
        float ws = s0 * sh[(n + 1) & (NN - 1)] + s1 * sh[n] + s2 * sh[(n - 1) & (NN - 1)];
        float p = __powf(ws, gamma);
        wp[j] = p; sp += p;
    }
    sp = blk_reduce(sp, red, false);
    const float invp = 1.f / (sp + 1e-8f);
    float* wout = g_w + (size_t)hb * NN;
#pragma unroll
    for (int j = 0; j < 8; j++) wout[t + 512 * j] = wp[j] * invp;
}

// ---------------- read partial reduction ----------------
__global__ void read_reduce_kernel() {
    int ridx = blockIdx.x, b = blockIdx.y, t = threadIdx.x;  // 64 threads
    float s = 0.f;
#pragma unroll
    for (int ch = 0; ch < 16; ch++)
        s += g_readp[(((size_t)ridx * BB + b) * 16 + ch) * 64 + t];
    g_hr[(size_t)b * 768 + 512 + ridx * 64 + t] = s;
}

// ---------------- output epilogue ----------------
__global__ void out_act_kernel(const float* __restrict__ b_out, float* __restrict__ out) {
    int b = blockIdx.x, j = threadIdx.x;  // 256 threads
    float v = g_op[(size_t)b * 256 + j] + g_op[((size_t)BB + b) * 256 + j] + b_out[j];
    out[(size_t)b * 256 + j] = 1.f / (1.f + expf(-v));
}

// ---------------- launch ----------------
extern "C" void kernel_launch(void* const* d_in, const int* in_sizes, int n_in,
                              void* d_out, int out_size) {
    const float* in_data      = (const float*)d_in[0];
    const float* memory       = (const float*)d_in[1];
    const float* h_prev       = (const float*)d_in[2];
    const float* c_prev       = (const float*)d_in[3];
    const float* prev_reads   = (const float*)d_in[4];
    const float* prev_weights = (const float*)d_in[5];
    const float* W_ih  = (const float*)d_in[6];
    const float* b_ih  = (const float*)d_in[7];
    const float* W_hh  = (const float*)d_in[8];
    const float* b_hh  = (const float*)d_in[9];
    const float* W_out = (const float*)d_in[10];
    const float* b_out = (const float*)d_in[11];
    const float* Wk    = (const float*)d_in[12];
    const float* bk    = (const float*)d_in[13];
    const float* Wbeta = (const float*)d_in[14];
    const float* bbeta = (const float*)d_in[15];
    const float* Wg    = (const float*)d_in[16];
    const float* bg    = (const float*)d_in[17];
    const float* Ws    = (const float*)d_in[18];
    const float* bs    = (const float*)d_in[19];
    const float* Wgam  = (const float*)d_in[20];
    const float* bgam  = (const float*)d_in[21];
    const float* We    = (const float*)d_in[22];
    const float* be    = (const float*)d_in[23];
    const float* Wa    = (const float*)d_in[24];
    const float* ba    = (const float*)d_in[25];
    float* out = (float*)d_out;

    float* gp; cudaGetSymbolAddress((void**)&gp, g_gp);
    float* pp; cudaGetSymbolAddress((void**)&pp, g_pp);
    float* op; cudaGetSymbolAddress((void**)&op, g_op);
    float* gx; cudaGetSymbolAddress((void**)&gx, g_x);
    float* gc; cudaGetSymbolAddress((void**)&gc, g_c);
    float* ghr; cudaGetSymbolAddress((void**)&ghr, g_hr);
    float* gWstk; cudaGetSymbolAddress((void**)&gWstk, g_Wstk);

    // 1. pack x and stacked head weights
    pack_x_kernel<<<(BB * 512 + 255) / 256, 256>>>(in_data, prev_reads);
    pack_w_kernel<<<(PR * 512 + 255) / 256, 256>>>(Wk, We, Wa, Ws, Wbeta, Wg, Wgam);

    // 2. LSTM gates GEMM: x@W_ih^T (slots 0,1) + h@W_hh^T (slots 2,3)
    gemm_tn<<<dim3(32, 2, 2), 256>>>(gx, W_ih, gp, 2048, 512, 256, 0);
    gemm_tn<<<dim3(32, 2, 2), 256>>>(h_prev, W_hh, gp, 2048, 512, 256, 2);
    lstm_act_kernel<<<(BB * 512 + 255) / 256, 256>>>(b_ih, b_hh, c_prev);

    // 3. head-param GEMM + activations
    gemm_tn<<<dim3(25, 2, 2), 256>>>(gc, gWstk, pp, PR, 512, 256, 0);
    param_act_kernel<<<dim3(8, BB), 64>>>(bk, be, ba, bs, bbeta, bg, bgam);

    // 4. memory passes interleaved with weight kernels
    pass_kernel<0><<<dim3(16, BB), 256>>>(memory);
    weight_kernel<<<dim3(2, BB), 512>>>(prev_weights, 0);
    pass_kernel<1><<<dim3(16, BB), 256>>>(memory);
    weight_kernel<<<dim3(2, BB), 512>>>(prev_weights, 2);
    pass_kernel<2><<<dim3(16, BB), 256>>>(memory);
    weight_kernel<<<dim3(2, BB), 512>>>(prev_weights, 4);
    pass_kernel<3><<<dim3(16, BB), 256>>>(memory);
    weight_kernel<<<dim3(1, BB), 512>>>(prev_weights, 6);
    pass_kernel<4><<<dim3(16, BB), 256>>>(memory);
    read_reduce_kernel<<<dim3(4, BB), 64>>>();

    // 5. output layer
    gemm_tn<<<dim3(4, 2, 2), 256>>>(ghr, W_out, op, 256, 768, 384, 0);
    out_act_kernel<<<BB, 256>>>(b_out, out);
}

// round 3
// speedup vs baseline: 1.1873x; 1.1873x over previous
#include <cuda_runtime.h>
#include <cuda_fp16.h>
#include <math.h>

#define BB 128
#define NN 4096
#define MM 64
#define HH 512
#define PR 1584   // stacked head-param rows: 512 Wk + 512 We + 512 Wa + 24 Ws + 8 Wbeta + 8 Wg + 8 Wgam

// ---------------- scratch (device globals; no allocations) ----------------
__device__ float g_x[BB * 512];            // [x | prev_reads] for LSTM
__device__ float g_c[BB * HH];
__device__ float g_hr[BB * 768];           // [h(512) | read0..3 (4*64)]
__device__ float g_Wstk[PR * 512];         // stacked head-param weights
__device__ float g_gp[8 * BB * 2048];      // gates GEMM split-K partials
__device__ float g_pp[4 * BB * PR];        // head-param GEMM partials
__device__ float g_op[6 * BB * 256];       // output GEMM partials
__device__ float g_keyv[8 * BB * MM];
__device__ float g_keynorm[8 * BB];
__device__ float g_ev[8 * BB * MM];
__device__ float g_av[8 * BB * MM];
__device__ float g_beta[8 * BB];
__device__ float g_gv[8 * BB];
__device__ float g_gamma[8 * BB];
__device__ float g_sv[8 * BB * 3];
__device__ float g_simA[BB * NN];
__device__ float g_simB[BB * NN];
__device__ float g_w[8 * BB * NN];         // final head weights (heads 0..6 used)
__device__ float g_readp[4 * BB * 16 * MM];// per-chunk read partials
__device__ __half g_memh[(size_t)BB * NN * MM];  // fp16 cache of original memory

__device__ __forceinline__ float sigf(float x) { return 1.f / (1.f + __expf(-x)); }
__device__ __forceinline__ float softplusf(float x) {
    return fmaxf(x, 0.f) + log1pf(expf(-fabsf(x)));
}

// ---------------- pack kernels ----------------
__global__ void pack_x_kernel(const float* __restrict__ in_data,
                              const float* __restrict__ prev_reads) {
    int idx = blockIdx.x * blockDim.x + threadIdx.x;
    if (idx >= BB * 512) return;
    int b = idx >> 9, c = idx & 511;
    float v;
    if (c < 256) v = in_data[b * 256 + c];
    else {
        int k = c - 256, i = k >> 6, m = k & 63;
        v = prev_reads[((size_t)i * BB + b) * MM + m];
    }
    g_x[idx] = v;
}

__global__ void pack_w_kernel(const float* __restrict__ Wk, const float* __restrict__ We,
                              const float* __restrict__ Wa, const float* __restrict__ Ws,
                              const float* __restrict__ Wbeta, const float* __restrict__ Wg,
                              const float* __restrict__ Wgam) {
    int idx = blockIdx.x * blockDim.x + threadIdx.x;
    if (idx >= PR * 512) return;
    int r = idx >> 9, k = idx & 511;
    float v;
    if (r < 512)        v = Wk[(size_t)r * 512 + k];
    else if (r < 1024)  v = We[(size_t)(r - 512) * 512 + k];
    else if (r < 1536)  v = Wa[(size_t)(r - 1024) * 512 + k];
    else if (r < 1560)  v = Ws[(size_t)(r - 1536) * 512 + k];
    else if (r < 1568)  v = Wbeta[(size_t)(r - 1560) * 512 + k];
    else if (r < 1576)  v = Wg[(size_t)(r - 1568) * 512 + k];
    else                v = Wgam[(size_t)(r - 1576) * 512 + k];
    g_Wstk[idx] = v;
}

// ---------------- split-K SGEMM: C[b,r] = sum_k A[b,k]*W[r,k] ----------------
// A [128,K] row-major, W [R,K] row-major. Partials into Cp[slot][128][R].
__global__ __launch_bounds__(256) void gemm_tn(
    const float* __restrict__ A, const float* __restrict__ W,
    float* __restrict__ Cp, int R, int K, int kChunk, int slotBase)
{
    __shared__ __align__(16) float As[16][68];
    __shared__ __align__(16) float Bs[16][68];
    const int t = threadIdx.x;
    const int tx = t & 15, ty = t >> 4;
    const int mBase = blockIdx.y * 64;
    const int rBase = blockIdx.x * 64;
    const int kStart = blockIdx.z * kChunk;
    const int slot = slotBase + blockIdx.z;
    const int loadRow = t >> 2;
    const int loadK = (t & 3) * 4;
    const float* Arow = A + (size_t)(mBase + loadRow) * K;
    const bool wv = (rBase + loadRow) < R;
    const float* Wrow = W + (size_t)(wv ? (rBase + loadRow) : 0) * K;
    float acc[4][4] = {};
    for (int k0 = kStart; k0 < kStart + kChunk; k0 += 16) {
        float4 a4 = *reinterpret_cast<const float4*>(Arow + k0 + loadK);
        float4 w4 = *reinterpret_cast<const float4*>(Wrow + k0 + loadK);
        if (!wv) w4 = make_float4(0.f, 0.f, 0.f, 0.f);
        __syncthreads();
        As[loadK + 0][loadRow] = a4.x; As[loadK + 1][loadRow] = a4.y;
        As[loadK + 2][loadRow] = a4.z; As[loadK + 3][loadRow] = a4.w;
        Bs[loadK + 0][loadRow] = w4.x; Bs[loadK + 1][loadRow] = w4.y;
        Bs[loadK + 2][loadRow] = w4.z; Bs[loadK + 3][loadRow] = w4.w;
        __syncthreads();
#pragma unroll
        for (int kk = 0; kk < 16; kk++) {
            float4 av = *reinterpret_cast<const float4*>(&As[kk][ty * 4]);
            float4 wvv = *reinterpret_cast<const float4*>(&Bs[kk][tx * 4]);
            float aa[4] = {av.x, av.y, av.z, av.w};
            float ww[4] = {wvv.x, wvv.y, wvv.z, wvv.w};
#pragma unroll
            for (int i = 0; i < 4; i++)
#pragma unroll
                for (int j = 0; j < 4; j++)
                    acc[i][j] = fmaf(aa[i], ww[j], acc[i][j]);
        }
    }
#pragma unroll
    for (int i = 0; i < 4; i++) {
        int m = mBase + ty * 4 + i;
#pragma unroll
        for (int j = 0; j < 4; j++) {
            int r = rBase + tx * 4 + j;
            if (r < R) Cp[((size_t)slot * BB + m) * R + r] = acc[i][j];
        }
    }
}

// ---------------- LSTM epilogue ----------------
__global__ void lstm_act_kernel(const float* __restrict__ b_ih, const float* __restrict__ b_hh,
                                const float* __restrict__ c_prev) {
    int idx = blockIdx.x * blockDim.x + threadIdx.x;
    if (idx >= BB * 512) return;
    int b = idx >> 9, j = idx & 511;
    float s[4];
#pragma unroll
    for (int q = 0; q < 4; q++) {
        int col = q * 512 + j;
        float v = b_ih[col] + b_hh[col];
#pragma unroll
        for (int sl = 0; sl < 8; sl++)
            v += g_gp[((size_t)sl * BB + b) * 2048 + col];
        s[q] = v;
    }
    float cc = sigf(s[1]) * c_prev[idx] + sigf(s[0]) * tanhf(s[2]);
    float hh = sigf(s[3]) * tanhf(cc);
    g_c[idx] = cc;
    g_hr[(size_t)b * 768 + j] = hh;
}

// ---------------- head-param epilogue ----------------
__global__ void param_act_kernel(const float* __restrict__ bk, const float* __restrict__ be,
                                 const float* __restrict__ ba, const float* __restrict__ bs,
                                 const float* __restrict__ bbeta, const float* __restrict__ bg,
                                 const float* __restrict__ bgam) {
    int head = blockIdx.x, b = blockIdx.y, t = threadIdx.x;  // 64 threads
    auto val = [&](int r) {
        float s = 0.f;
#pragma unroll
        for (int sl = 0; sl < 4; sl++) s += g_pp[((size_t)sl * BB + b) * PR + r];
        return s;
    };
    int hb = head * BB + b;

    float kv = val(head * 64 + t) + bk[head * 64 + t];
    g_keyv[(size_t)hb * 64 + t] = kv;
    // norm over 64 threads (2 warps)
    __shared__ float sh2[2];
    __shared__ float s3sh[3];
    float ns = kv * kv;
#pragma unroll
    for (int off = 16; off >= 1; off >>= 1) ns += __shfl_xor_sync(0xffffffffu, ns, off);
    if ((t & 31) == 0) sh2[t >> 5] = ns;

    g_ev[(size_t)hb * 64 + t] = sigf(val(512 + head * 64 + t) + be[head * 64 + t]);
    g_av[(size_t)hb * 64 + t] = tanhf(val(1024 + head * 64 + t) + ba[head * 64 + t]);
    if (t < 3) s3sh[t] = val(1536 + head * 3 + t) + bs[head * 3 + t];
    __syncthreads();
    if (t == 0) g_keynorm[hb] = sqrtf(sh2[0] + sh2[1]);
    if (t < 3) {
        float m = fmaxf(s3sh[0], fmaxf(s3sh[1], s3sh[2]));
        float d = expf(s3sh[0] - m) + expf(s3sh[1] - m) + expf(s3sh[2] - m);
        g_sv[(size_t)hb * 3 + t] = expf(s3sh[t] - m) / d;
    }
    if (t == 0) {
        g_beta[hb]  = softplusf(val(1560 + head) + bbeta[head]);
        g_gv[hb]    = sigf(val(1568 + head) + bg[head]);
        g_gamma[hb] = 1.f + softplusf(val(1576 + head) + bgam[head]);
    }
}

// ---------------- memory pass kernels ----------------
__device__ __forceinline__ void upd_row(float4& v, float w, const float4& e, const float4& a) {
    v.x = fmaf(w, fmaf(-e.x, v.x, a.x), v.x);
    v.y = fmaf(w, fmaf(-e.y, v.y, a.y), v.y);
    v.z = fmaf(w, fmaf(-e.z, v.z, a.z), v.z);
    v.w = fmaf(w, fmaf(-e.w, v.w, a.w), v.w);
}

// ST=0: sims h0,h1 on S0; also writes fp16 memory cache.
// ST=1: read h0 (S0), upd h1, sims h2,h3 (S1).
// ST=2: upd h1, read h2 (S1), upd h3, sims h4,h5 (S2).
// ST=3: upd h1,h3, read h4 (S2), upd h5, sim h6 (S3).
// ST=4: upd h1,h3,h5, read h6 (S3).
template <int ST>
__global__ __launch_bounds__(256) void pass_kernel(const float* __restrict__ mem) {
    constexpr bool HAS_READ = (ST >= 1);
    constexpr int READ_HEAD = (ST == 1) ? 0 : (ST == 2) ? 2 : (ST == 3) ? 4 : 6;
    constexpr int RIDX = READ_HEAD / 2;
    constexpr bool HAS_POST = (ST >= 1 && ST <= 3);
    constexpr int POST_HEAD = 2 * ST - 1;
    constexpr int NSIM = (ST <= 2) ? 2 : (ST == 3) ? 1 : 0;
    constexpr int SH0 = 2 * ST;

    const int b = blockIdx.y;
    const int lane = threadIdx.x & 31;
    const int warpId = threadIdx.x >> 5;
    const int li = lane & 15;
    const int half = lane >> 4;
    const int m4 = li * 4;

    auto ldvec = [&](const float* base, int head) -> float4 {
        return *reinterpret_cast<const float4*>(base + ((size_t)head * BB + b) * 64 + m4);
    };

    float4 e1, a1, e3, a3, e5, a5, k0v, k1v;
    float kn0 = 0.f, kn1 = 0.f;
    if (ST >= 1) { e1 = ldvec(g_ev, 1); a1 = ldvec(g_av, 1); }
    if (ST >= 2) { e3 = ldvec(g_ev, 3); a3 = ldvec(g_av, 3); }
    if (ST >= 3) { e5 = ldvec(g_ev, 5); a5 = ldvec(g_av, 5); }
    if (NSIM >= 1) { k0v = ldvec(g_keyv, SH0); kn0 = g_keynorm[SH0 * BB + b]; }
    if (NSIM >= 2) { k1v = ldvec(g_keyv, SH0 + 1); kn1 = g_keynorm[(SH0 + 1) * BB + b]; }

    float r0 = 0.f, r1 = 0.f, r2 = 0.f, r3 = 0.f;
    const int nBase = blockIdx.x * 256 + warpId * 32 + half;
    const size_t bn = (size_t)b * NN;

#pragma unroll 4
    for (int i = 0; i < 16; i++) {
        const int n = nBase + 2 * i;
        const size_t eidx = (bn + n) * 64 + m4;
        float4 v;
        if (ST == 0) {
            v = __ldg(reinterpret_cast<const float4*>(mem + eidx));
            __half2 p0 = __floats2half2_rn(v.x, v.y);
            __half2 p1 = __floats2half2_rn(v.z, v.w);
            uint2 st;
            st.x = *reinterpret_cast<unsigned*>(&p0);
            st.y = *reinterpret_cast<unsigned*>(&p1);
            *reinterpret_cast<uint2*>(g_memh + eidx) = st;
        } else {
            uint2 u = __ldg(reinterpret_cast<const uint2*>(g_memh + eidx));
            __half2 p0 = *reinterpret_cast<__half2*>(&u.x);
            __half2 p1 = *reinterpret_cast<__half2*>(&u.y);
            float2 f0 = __half22float2(p0);
            float2 f1 = __half22float2(p1);
            v = make_float4(f0.x, f0.y, f1.x, f1.y);
        }
        if (ST >= 2) { float w = __ldg(&g_w[((size_t)1 * BB + b) * NN + n]); upd_row(v, w, e1, a1); }
        if (ST >= 3) { float w = __ldg(&g_w[((size_t)3 * BB + b) * NN + n]); upd_row(v, w, e3, a3); }
        if (ST == 4) { float w = __ldg(&g_w[((size_t)5 * BB + b) * NN + n]); upd_row(v, w, e5, a5); }
        if (HAS_READ) {
            float wr = __ldg(&g_w[((size_t)READ_HEAD * BB + b) * NN + n]);
            r0 = fmaf(wr, v.x, r0); r1 = fmaf(wr, v.y, r1);
            r2 = fmaf(wr, v.z, r2); r3 = fmaf(wr, v.w, r3);
        }
        if (HAS_POST) {
            float w = __ldg(&g_w[((size_t)POST_HEAD * BB + b) * NN + n]);
            if (ST == 1) upd_row(v, w, e1, a1);
            else if (ST == 2) upd_row(v, w, e3, a3);
            else upd_row(v, w, e5, a5);
        }
        if (NSIM >= 1) {
            float ns = v.x * v.x + v.y * v.y + v.z * v.z + v.w * v.w;
            float d0 = v.x * k0v.x + v.y * k0v.y + v.z * k0v.z + v.w * k0v.w;
            float d1 = 0.f;
            if (NSIM >= 2) d1 = v.x * k1v.x + v.y * k1v.y + v.z * k1v.z + v.w * k1v.w;
#pragma unroll
            for (int off = 8; off >= 1; off >>= 1) {
                ns += __shfl_xor_sync(0xffffffffu, ns, off);
                d0 += __shfl_xor_sync(0xffffffffu, d0, off);
                if (NSIM >= 2) d1 += __shfl_xor_sync(0xffffffffu, d1, off);
            }
            if (li == 0) {
                float nm = sqrtf(ns);
                g_simA[bn + n] = d0 / (nm * kn0 + 1e-8f);
                if (NSIM >= 2) g_simB[bn + n] = d1 / (nm * kn1 + 1e-8f);
            }
        }
    }

    if (HAS_READ) {
        __shared__ float sred[8][64];
        r0 += __shfl_down_sync(0xffffffffu, r0, 16);
        r1 += __shfl_down_sync(0xffffffffu, r1, 16);
        r2 += __shfl_down_sync(0xffffffffu, r2, 16);
        r3 += __shfl_down_sync(0xffffffffu, r3, 16);
        if (lane < 16) {
            sred[warpId][m4 + 0] = r0; sred[warpId][m4 + 1] = r1;
            sred[warpId][m4 + 2] = r2; sred[warpId][m4 + 3] = r3;
        }
        __syncthreads();
        if (threadIdx.x < 64) {
            float s = 0.f;
#pragma unroll
            for (int w = 0; w < 8; w++) s += sred[w][threadIdx.x];
            g_readp[(((size_t)RIDX * BB + b) * 16 + blockIdx.x) * 64 + threadIdx.x] = s;
        }
    }
}

// ---------------- per-head weight kernel (softmax/interp/shift/sharpen) ----------------
__device__ __forceinline__ float blk_reduce(float v, float* red, bool isMax) {
    int lane = threadIdx.x & 31, wid = threadIdx.x >> 5;
#pragma unroll
    for (int off = 16; off >= 1; off >>= 1) {
        float o = __shfl_xor_sync(0xffffffffu, v, off);
        v = isMax ? fmaxf(v, o) : (v + o);
    }
    if (lane == 0) red[wid] = v;
    __syncthreads();
    if (wid == 0) {
        float x = (lane < 16) ? red[lane] : (isMax ? -1e30f : 0.f);
#pragma unroll
        for (int off = 8; off >= 1; off >>= 1) {
            float o = __shfl_xor_sync(0xffffffffu, x, off);
            x = isMax ? fmaxf(x, o) : (x + o);
        }
        if (lane == 0) red[0] = x;
    }
    __syncthreads();
    float r = red[0];
    __syncthreads();
    return r;
}

__global__ __launch_bounds__(512) void weight_kernel(const float* __restrict__ prev_weights,
                                                     int headBase) {
    __shared__ float sh[NN];
    __shared__ float red[16];
    const int hIdx = blockIdx.x;
    const int head = headBase + hIdx;
    const int b = blockIdx.y;
    const int t = threadIdx.x;
    const int hb = head * BB + b;
    const float* sim = (hIdx == 0 ? g_simA : g_simB) + (size_t)b * NN;
    const float* pw = prev_weights + (size_t)hb * NN;

    const float beta = g_beta[hb], gg = g_gv[hb], gamma = g_gamma[hb];
    const float s0 = g_sv[(size_t)hb * 3 + 0];
    const float s1 = g_sv[(size_t)hb * 3 + 1];
    const float s2 = g_sv[(size_t)hb * 3 + 2];

    float tv[8];
    float mx = -1e30f;
#pragma unroll
    for (int j = 0; j < 8; j++) {
        tv[j] = beta * sim[t + 512 * j];
        mx = fmaxf(mx, tv[j]);
    }
    mx = blk_reduce(mx, red, true);
    float se = 0.f, ev[8];
#pragma unroll
    for (int j = 0; j < 8; j++) { ev[j] = __expf(tv[j] - mx); se += ev[j]; }
    se = blk_reduce(se, red, false);
    const float inv = 1.f / se;
#pragma unroll
    for (int j = 0; j < 8; j++) {
        int n = t + 512 * j;
        sh[n] = gg * (ev[j] * inv) + (1.f - gg) * pw[n];
    }
    __syncthreads();
    float sp = 0.f, wp[8];
#pragma unroll
    for (int j = 0; j < 8; j++) {
        int n = t + 512 * j;
        float ws = s0 * sh[(n + 1) & (NN - 1)] + s1 * sh[n] + s2 * sh[(n - 1) & (NN - 1)];
        float p = __powf(ws, gamma);
        wp[j] = p; sp += p;
    }
    sp = blk_reduce(sp, red, false);
    const float invp = 1.f / (sp + 1e-8f);
    float* wout = g_w + (size_t)hb * NN;
#pragma unroll
    for (int j = 0; j < 8; j++) wout[t + 512 * j] = wp[j] * invp;
}

// ---------------- read partial reduction ----------------
__global__ void read_reduce_kernel() {
    int ridx = blockIdx.x, b = blockIdx.y, t = threadIdx.x;  // 64 threads
    float s = 0.f;
#pragma unroll
    for (int ch = 0; ch < 16; ch++)
        s += g_readp[(((size_t)ridx * BB + b) * 16 + ch) * 64 + t];
    g_hr[(size_t)b * 768 + 512 + ridx * 64 + t] = s;
}

// ---------------- output epilogue ----------------
__global__ void out_act_kernel(const float* __restrict__ b_out, float* __restrict__ out) {
    int b = blockIdx.x, j = threadIdx.x;  // 256 threads
    float v = b_out[j];
#pragma unroll
    for (int sl = 0; sl < 6; sl++)
        v += g_op[((size_t)sl * BB + b) * 256 + j];
    out[(size_t)b * 256 + j] = 1.f / (1.f + expf(-v));
}

// ---------------- launch ----------------
extern "C" void kernel_launch(void* const* d_in, const int* in_sizes, int n_in,
                              void* d_out, int out_size) {
    const float* in_data      = (const float*)d_in[0];
    const float* memory       = (const float*)d_in[1];
    const float* h_prev       = (const float*)d_in[2];
    const float* c_prev       = (const float*)d_in[3];
    const float* prev_reads   = (const float*)d_in[4];
    const float* prev_weights = (const float*)d_in[5];
    const float* W_ih  = (const float*)d_in[6];
    const float* b_ih  = (const float*)d_in[7];
    const float* W_hh  = (const float*)d_in[8];
    const float* b_hh  = (const float*)d_in[9];
    const float* W_out = (const float*)d_in[10];
    const float* b_out = (const float*)d_in[11];
    const float* Wk    = (const float*)d_in[12];
    const float* bk    = (const float*)d_in[13];
    const float* Wbeta = (const float*)d_in[14];
    const float* bbeta = (const float*)d_in[15];
    const float* Wg    = (const float*)d_in[16];
    const float* bg    = (const float*)d_in[17];
    const float* Ws    = (const float*)d_in[18];
    const float* bs    = (const float*)d_in[19];
    const float* Wgam  = (const float*)d_in[20];
    const float* bgam  = (const float*)d_in[21];
    const float* We    = (const float*)d_in[22];
    const float* be    = (const float*)d_in[23];
    const float* Wa    = (const float*)d_in[24];
    const float* ba    = (const float*)d_in[25];
    float* out = (float*)d_out;

    float* gp; cudaGetSymbolAddress((void**)&gp, g_gp);
    float* pp; cudaGetSymbolAddress((void**)&pp, g_pp);
    float* op; cudaGetSymbolAddress((void**)&op, g_op);
    float* gx; cudaGetSymbolAddress((void**)&gx, g_x);
    float* gc; cudaGetSymbolAddress((void**)&gc, g_c);
    float* ghr; cudaGetSymbolAddress((void**)&ghr, g_hr);
    float* gWstk; cudaGetSymbolAddress((void**)&gWstk, g_Wstk);

    // 1. pack x and stacked head weights
    pack_x_kernel<<<(BB * 512 + 255) / 256, 256>>>(in_data, prev_reads);
    pack_w_kernel<<<(PR * 512 + 255) / 256, 256>>>(Wk, We, Wa, Ws, Wbeta, Wg, Wgam);

    // 2. LSTM gates GEMM: x@W_ih^T (slots 0..3) + h@W_hh^T (slots 4..7)
    gemm_tn<<<dim3(32, 2, 4), 256>>>(gx, W_ih, gp, 2048, 512, 128, 0);
    gemm_tn<<<dim3(32, 2, 4), 256>>>(h_prev, W_hh, gp, 2048, 512, 128, 4);
    lstm_act_kernel<<<(BB * 512 + 255) / 256, 256>>>(b_ih, b_hh, c_prev);

    // 3. head-param GEMM + activations
    gemm_tn<<<dim3(25, 2, 4), 256>>>(gc, gWstk, pp, PR, 512, 128, 0);
    param_act_kernel<<<dim3(8, BB), 64>>>(bk, be, ba, bs, bbeta, bg, bgam);

    // 4. memory passes interleaved with weight kernels
    pass_kernel<0><<<dim3(16, BB), 256>>>(memory);
    weight_kernel<<<dim3(2, BB), 512>>>(prev_weights, 0);
    pass_kernel<1><<<dim3(16, BB), 256>>>(memory);
    weight_kernel<<<dim3(2, BB), 512>>>(prev_weights, 2);
    pass_kernel<2><<<dim3(16, BB), 256>>>(memory);
    weight_kernel<<<dim3(2, BB), 512>>>(prev_weights, 4);
    pass_kernel<3><<<dim3(16, BB), 256>>>(memory);
    weight_kernel<<<dim3(1, BB), 512>>>(prev_weights, 6);
    pass_kernel<4><<<dim3(16, BB), 256>>>(memory);
    read_reduce_kernel<<<dim3(4, BB), 64>>>();

    // 5. output layer
    gemm_tn<<<dim3(4, 2, 6), 256>>>(ghr, W_out, op, 256, 768, 128, 0);
    out_act_kernel<<<BB, 256>>>(b_out, out);
}

// round 5
// speedup vs baseline: 1.2900x; 1.0865x over previous
#include <cuda_runtime.h>
#include <cuda_fp16.h>
#include <math.h>

#define BB 128
#define NN 4096
#define MM 64
#define HH 512
#define PR 1584   // stacked: 512 Wk + 512 We + 512 Wa + 24 Ws + 8 Wbeta + 8 Wg + 8 Wgam

// ---------------- scratch (device globals; no allocations) ----------------
__device__ float g_x[BB * 512];
__device__ float g_c[BB * HH];
__device__ float g_hr[BB * 768];           // [h(512) | read0..3 (4*64)]
__device__ float g_Wstk[PR * 512];
__device__ float g_gp[16 * BB * 2048];     // gates GEMM split-K partials
__device__ float g_pp[8 * BB * PR];        // head-param GEMM partials
__device__ float g_op[6 * BB * 256];       // output GEMM partials
__device__ float g_keyv[8 * BB * MM];
__device__ float g_keynorm[8 * BB];
__device__ float g_ev[8 * BB * MM];
__device__ float g_av[8 * BB * MM];
__device__ float g_beta[8 * BB];
__device__ float g_gv[8 * BB];
__device__ float g_gamma[8 * BB];
__device__ float g_sv[8 * BB * 3];
__device__ float g_w[8 * BB * NN];         // final head weights (heads 0..6 used)
__device__ __half g_memh[(size_t)BB * NN * MM];  // fp16 cache of original memory

__device__ __forceinline__ float sigf(float x) { return 1.f / (1.f + __expf(-x)); }
__device__ __forceinline__ float softplusf(float x) {
    return fmaxf(x, 0.f) + log1pf(expf(-fabsf(x)));
}

// ---------------- combined pack kernel ----------------
__global__ void pack_all_kernel(const float* __restrict__ in_data,
                                const float* __restrict__ prev_reads,
                                const float* __restrict__ Wk, const float* __restrict__ We,
                                const float* __restrict__ Wa, const float* __restrict__ Ws,
                                const float* __restrict__ Wbeta, const float* __restrict__ Wg,
                                const float* __restrict__ Wgam) {
    int idx = blockIdx.x * blockDim.x + threadIdx.x;
    if (idx < BB * 512) {
        int b = idx >> 9, c = idx & 511;
        float v;
        if (c < 256) v = in_data[b * 256 + c];
        else {
            int k = c - 256, i = k >> 6, m = k & 63;
            v = prev_reads[((size_t)i * BB + b) * MM + m];
        }
        g_x[idx] = v;
        return;
    }
    int j = idx - BB * 512;
    if (j >= PR * 512) return;
    int r = j >> 9, k = j & 511;
    float v;
    if (r < 512)        v = Wk[(size_t)r * 512 + k];
    else if (r < 1024)  v = We[(size_t)(r - 512) * 512 + k];
    else if (r < 1536)  v = Wa[(size_t)(r - 1024) * 512 + k];
    else if (r < 1560)  v = Ws[(size_t)(r - 1536) * 512 + k];
    else if (r < 1568)  v = Wbeta[(size_t)(r - 1560) * 512 + k];
    else if (r < 1576)  v = Wg[(size_t)(r - 1568) * 512 + k];
    else                v = Wgam[(size_t)(r - 1576) * 512 + k];
    g_Wstk[j] = v;
}

// ---------------- split-K SGEMM: C[b,r] = sum_k A[b,k]*W[r,k] ----------------
__global__ __launch_bounds__(256) void gemm_tn(
    const float* __restrict__ A, const float* __restrict__ W,
    float* __restrict__ Cp, int R, int K, int kChunk, int slotBase)
{
    __shared__ __align__(16) float As[16][68];
    __shared__ __align__(16) float Bs[16][68];
    const int t = threadIdx.x;
    const int tx = t & 15, ty = t >> 4;
    const int mBase = blockIdx.y * 64;
    const int rBase = blockIdx.x * 64;
    const int kStart = blockIdx.z * kChunk;
    const int slot = slotBase + blockIdx.z;
    const int loadRow = t >> 2;
    const int loadK = (t & 3) * 4;
    const float* Arow = A + (size_t)(mBase + loadRow) * K;
    const bool wv = (rBase + loadRow) < R;
    const float* Wrow = W + (size_t)(wv ? (rBase + loadRow) : 0) * K;
    float acc[4][4] = {};
    for (int k0 = kStart; k0 < kStart + kChunk; k0 += 16) {
        float4 a4 = *reinterpret_cast<const float4*>(Arow + k0 + loadK);
        float4 w4 = *reinterpret_cast<const float4*>(Wrow + k0 + loadK);
        if (!wv) w4 = make_float4(0.f, 0.f, 0.f, 0.f);
        __syncthreads();
        As[loadK + 0][loadRow] = a4.x; As[loadK + 1][loadRow] = a4.y;
        As[loadK + 2][loadRow] = a4.z; As[loadK + 3][loadRow] = a4.w;
        Bs[loadK + 0][loadRow] = w4.x; Bs[loadK + 1][loadRow] = w4.y;
        Bs[loadK + 2][loadRow] = w4.z; Bs[loadK + 3][loadRow] = w4.w;
        __syncthreads();
#pragma unroll
        for (int kk = 0; kk < 16; kk++) {
            float4 av = *reinterpret_cast<const float4*>(&As[kk][ty * 4]);
            float4 wvv = *reinterpret_cast<const float4*>(&Bs[kk][tx * 4]);
            float aa[4] = {av.x, av.y, av.z, av.w};
            float ww[4] = {wvv.x, wvv.y, wvv.z, wvv.w};
#pragma unroll
            for (int i = 0; i < 4; i++)
#pragma unroll
                for (int j = 0; j < 4; j++)
                    acc[i][j] = fmaf(aa[i], ww[j], acc[i][j]);
        }
    }
#pragma unroll
    for (int i = 0; i < 4; i++) {
        int m = mBase + ty * 4 + i;
#pragma unroll
        for (int j = 0; j < 4; j++) {
            int r = rBase + tx * 4 + j;
            if (r < R) Cp[((size_t)slot * BB + m) * R + r] = acc[i][j];
        }
    }
}

// ---------------- LSTM epilogue ----------------
__global__ void lstm_act_kernel(const float* __restrict__ b_ih, const float* __restrict__ b_hh,
                                const float* __restrict__ c_prev) {
    int idx = blockIdx.x * blockDim.x + threadIdx.x;
    if (idx >= BB * 512) return;
    int b = idx >> 9, j = idx & 511;
    float s[4];
#pragma unroll
    for (int q = 0; q < 4; q++) {
        int col = q * 512 + j;
        float v = b_ih[col] + b_hh[col];
#pragma unroll
        for (int sl = 0; sl < 16; sl++)
            v += g_gp[((size_t)sl * BB + b) * 2048 + col];
        s[q] = v;
    }
    float cc = sigf(s[1]) * c_prev[idx] + sigf(s[0]) * tanhf(s[2]);
    float hh = sigf(s[3]) * tanhf(cc);
    g_c[idx] = cc;
    g_hr[(size_t)b * 768 + j] = hh;
}

// ---------------- head-param epilogue ----------------
__global__ void param_act_kernel(const float* __restrict__ bk, const float* __restrict__ be,
                                 const float* __restrict__ ba, const float* __restrict__ bs,
                                 const float* __restrict__ bbeta, const float* __restrict__ bg,
                                 const float* __restrict__ bgam) {
    int head = blockIdx.x, b = blockIdx.y, t = threadIdx.x;  // 64 threads
    auto val = [&](int r) {
        float s = 0.f;
#pragma unroll
        for (int sl = 0; sl < 8; sl++) s += g_pp[((size_t)sl * BB + b) * PR + r];
        return s;
    };
    int hb = head * BB + b;

    float kv = val(head * 64 + t) + bk[head * 64 + t];
    g_keyv[(size_t)hb * 64 + t] = kv;
    __shared__ float sh2[2];
    __shared__ float s3sh[3];
    float ns = kv * kv;
#pragma unroll
    for (int off = 16; off >= 1; off >>= 1) ns += __shfl_xor_sync(0xffffffffu, ns, off);
    if ((t & 31) == 0) sh2[t >> 5] = ns;

    g_ev[(size_t)hb * 64 + t] = sigf(val(512 + head * 64 + t) + be[head * 64 + t]);
    g_av[(size_t)hb * 64 + t] = tanhf(val(1024 + head * 64 + t) + ba[head * 64 + t]);
    if (t < 3) s3sh[t] = val(1536 + head * 3 + t) + bs[head * 3 + t];
    __syncthreads();
    if (t == 0) g_keynorm[hb] = sqrtf(sh2[0] + sh2[1]);
    if (t < 3) {
        float m = fmaxf(s3sh[0], fmaxf(s3sh[1], s3sh[2]));
        float d = expf(s3sh[0] - m) + expf(s3sh[1] - m) + expf(s3sh[2] - m);
        g_sv[(size_t)hb * 3 + t] = expf(s3sh[t] - m) / d;
    }
    if (t == 0) {
        g_beta[hb]  = softplusf(val(1560 + head) + bbeta[head]);
        g_gv[hb]    = sigf(val(1568 + head) + bg[head]);
        g_gamma[hb] = 1.f + softplusf(val(1576 + head) + bgam[head]);
    }
}

// ---------------- fused pass + weight kernel ----------------
__device__ __forceinline__ void upd_row(float4& v, float w, const float4& e, const float4& a) {
    v.x = fmaf(w, fmaf(-e.x, v.x, a.x), v.x);
    v.y = fmaf(w, fmaf(-e.y, v.y, a.y), v.y);
    v.z = fmaf(w, fmaf(-e.z, v.z, a.z), v.z);
    v.w = fmaf(w, fmaf(-e.w, v.w, a.w), v.w);
}

// 1024-thread block reduce
__device__ __forceinline__ float blk_reduce32(float v, float* red, bool isMax) {
    int lane = threadIdx.x & 31, wid = threadIdx.x >> 5;
#pragma unroll
    for (int off = 16; off >= 1; off >>= 1) {
        float o = __shfl_xor_sync(0xffffffffu, v, off);
        v = isMax ? fmaxf(v, o) : (v + o);
    }
    if (lane == 0) red[wid] = v;
    __syncthreads();
    if (wid == 0) {
        float x = red[lane];
#pragma unroll
        for (int off = 16; off >= 1; off >>= 1) {
            float o = __shfl_xor_sync(0xffffffffu, x, off);
            x = isMax ? fmaxf(x, o) : (x + o);
        }
        if (lane == 0) red[0] = x;
    }
    __syncthreads();
    float r = red[0];
    __syncthreads();
    return r;
}

// dynamic smem: [simA 4096][simB 4096][wg 4096 (also sred alias)][red 32]
#define PASS_SMEM ((3 * 4096 + 32) * 4)

// ST=0: fp32 load + fp16 store; sims h0,h1; weights h0,h1.
// ST=1: read h0, post-upd w1; sims h2,h3; weights h2,h3.
// ST=2: upd w1, read h2, post-upd w3; sims h4,h5; weights h4,h5.
// ST=3: upd w1,w3, read h4, post-upd w5; sim h6; weight h6.
// ST=4: upd w1,w3,w5, read h6.
template <int ST>
__global__ __launch_bounds__(1024, 1) void pass_fused(const float* __restrict__ mem,
                                                      const float* __restrict__ prev_weights) {
    constexpr bool HAS_READ = (ST >= 1);
    constexpr int READ_HEAD = (ST == 1) ? 0 : (ST == 2) ? 2 : (ST == 3) ? 4 : 6;
    constexpr int RIDX = READ_HEAD / 2;
    constexpr bool HAS_POST = (ST >= 1 && ST <= 3);
    constexpr int POST_HEAD = 2 * ST - 1;
    constexpr int NSIM = (ST <= 2) ? 2 : (ST == 3) ? 1 : 0;
    constexpr int SH0 = 2 * ST;

    extern __shared__ float smem[];
    float* s_simA = smem;
    float* s_simB = smem + 4096;
    float* s_wg   = smem + 8192;   // aliased as sred[32][64] during phase A tail
    float* s_red  = smem + 12288;

    const int b = blockIdx.x;
    const int tid = threadIdx.x;
    const int lane = tid & 31;
    const int warpId = tid >> 5;
    const int li = lane & 15;
    const int half = lane >> 4;
    const int m4 = li * 4;

    auto ldvec = [&](const float* base, int head) -> float4 {
        return *reinterpret_cast<const float4*>(base + ((size_t)head * BB + b) * 64 + m4);
    };

    float4 e1, a1, e3, a3, e5, a5, k0v, k1v;
    float kn0 = 0.f, kn1 = 0.f;
    if (ST >= 1) { e1 = ldvec(g_ev, 1); a1 = ldvec(g_av, 1); }
    if (ST >= 2) { e3 = ldvec(g_ev, 3); a3 = ldvec(g_av, 3); }
    if (ST >= 3) { e5 = ldvec(g_ev, 5); a5 = ldvec(g_av, 5); }
    if (NSIM >= 1) { k0v = ldvec(g_keyv, SH0); kn0 = g_keynorm[SH0 * BB + b]; }
    if (NSIM >= 2) { k1v = ldvec(g_keyv, SH0 + 1); kn1 = g_keynorm[(SH0 + 1) * BB + b]; }

    float r0 = 0.f, r1 = 0.f, r2 = 0.f, r3 = 0.f;
    const size_t bn = (size_t)b * NN;
    const int rowInBlk = warpId * 2 + half;  // 0..63

    // ---------------- phase A: stream memory rows ----------------
#pragma unroll 4
    for (int it = 0; it < 64; it++) {
        const int n = it * 64 + rowInBlk;
        const size_t eidx = (bn + n) * 64 + m4;
        float4 v;
        if (ST == 0) {
            v = __ldcs(reinterpret_cast<const float4*>(mem + eidx));
            __half2 p0 = __floats2half2_rn(v.x, v.y);
            __half2 p1 = __floats2half2_rn(v.z, v.w);
            uint2 st;
            st.x = *reinterpret_cast<unsigned*>(&p0);
            st.y = *reinterpret_cast<unsigned*>(&p1);
            *reinterpret_cast<uint2*>(g_memh + eidx) = st;
        } else {
            uint2 u = __ldg(reinterpret_cast<const uint2*>(g_memh + eidx));
            float2 f0 = __half22float2(*reinterpret_cast<__half2*>(&u.x));
            float2 f1 = __half22float2(*reinterpret_cast<__half2*>(&u.y));
            v = make_float4(f0.x, f0.y, f1.x, f1.y);
        }
        if (ST >= 2) { float w = __ldg(&g_w[((size_t)1 * BB + b) * NN + n]); upd_row(v, w, e1, a1); }
        if (ST >= 3) { float w = __ldg(&g_w[((size_t)3 * BB + b) * NN + n]); upd_row(v, w, e3, a3); }
        if (ST == 4) { float w = __ldg(&g_w[((size_t)5 * BB + b) * NN + n]); upd_row(v, w, e5, a5); }
        if (HAS_READ) {
            float wr = __ldg(&g_w[((size_t)READ_HEAD * BB + b) * NN + n]);
            r0 = fmaf(wr, v.x, r0); r1 = fmaf(wr, v.y, r1);
            r2 = fmaf(wr, v.z, r2); r3 = fmaf(wr, v.w, r3);
        }
        if (HAS_POST) {
            float w = __ldg(&g_w[((size_t)POST_HEAD * BB + b) * NN + n]);
            if (ST == 1) upd_row(v, w, e1, a1);
            else if (ST == 2) upd_row(v, w, e3, a3);
            else upd_row(v, w, e5, a5);
        }
        if (NSIM >= 1) {
            float ns = v.x * v.x + v.y * v.y + v.z * v.z + v.w * v.w;
            float d0 = v.x * k0v.x + v.y * k0v.y + v.z * k0v.z + v.w * k0v.w;
            float d1 = 0.f;
            if (NSIM >= 2) d1 = v.x * k1v.x + v.y * k1v.y + v.z * k1v.z + v.w * k1v.w;
#pragma unroll
            for (int off = 8; off >= 1; off >>= 1) {
                ns += __shfl_xor_sync(0xffffffffu, ns, off);
                d0 += __shfl_xor_sync(0xffffffffu, d0, off);
                if (NSIM >= 2) d1 += __shfl_xor_sync(0xffffffffu, d1, off);
            }
            if (li == 0) {
                float nm = sqrtf(ns);
                s_simA[n] = d0 / (nm * kn0 + 1e-8f);
                if (NSIM >= 2) s_simB[n] = d1 / (nm * kn1 + 1e-8f);
            }
        }
    }

    // in-block read reduction -> g_hr
    if (HAS_READ) {
        r0 += __shfl_down_sync(0xffffffffu, r0, 16);
        r1 += __shfl_down_sync(0xffffffffu, r1, 16);
        r2 += __shfl_down_sync(0xffffffffu, r2, 16);
        r3 += __shfl_down_sync(0xffffffffu, r3, 16);
        if (lane < 16) {
            s_wg[warpId * 64 + m4 + 0] = r0; s_wg[warpId * 64 + m4 + 1] = r1;
            s_wg[warpId * 64 + m4 + 2] = r2; s_wg[warpId * 64 + m4 + 3] = r3;
        }
        __syncthreads();
        if (tid < 64) {
            float s = 0.f;
#pragma unroll
            for (int w = 0; w < 32; w++) s += s_wg[w * 64 + tid];
            g_hr[(size_t)b * 768 + 512 + RIDX * 64 + tid] = s;
        }
    }
    __syncthreads();

    // ---------------- phase B: weights for freshly computed sims ----------------
#pragma unroll
    for (int hh = 0; hh < NSIM; hh++) {
        const int head = SH0 + hh;
        const int hb = head * BB + b;
        const float* sim = hh ? s_simB : s_simA;
        const float* pw = prev_weights + (size_t)hb * NN;
        const float beta = g_beta[hb], gg = g_gv[hb], gamma = g_gamma[hb];
        const float s0 = g_sv[(size_t)hb * 3 + 0];
        const float s1 = g_sv[(size_t)hb * 3 + 1];
        const float s2 = g_sv[(size_t)hb * 3 + 2];

        float tv[4];
        float mx = -1e30f;
#pragma unroll
        for (int j = 0; j < 4; j++) {
            tv[j] = beta * sim[tid + 1024 * j];
            mx = fmaxf(mx, tv[j]);
        }
        mx = blk_reduce32(mx, s_red, true);
        float se = 0.f, evv[4];
#pragma unroll
        for (int j = 0; j < 4; j++) { evv[j] = __expf(tv[j] - mx); se += evv[j]; }
        se = blk_reduce32(se, s_red, false);
        const float inv = 1.f / se;
#pragma unroll
        for (int j = 0; j < 4; j++) {
            int n = tid + 1024 * j;
            s_wg[n] = gg * (evv[j] * inv) + (1.f - gg) * pw[n];
        }
        __syncthreads();
        float sp = 0.f, wp[4];
#pragma unroll
        for (int j = 0; j < 4; j++) {
            int n = tid + 1024 * j;
            float ws = s0 * s_wg[(n + 1) & (NN - 1)] + s1 * s_wg[n] + s2 * s_wg[(n - 1) & (NN - 1)];
            float p = __powf(ws, gamma);
            wp[j] = p; sp += p;
        }
        sp = blk_reduce32(sp, s_red, false);
        const float invp = 1.f / (sp + 1e-8f);
        float* wout = g_w + (size_t)hb * NN;
#pragma unroll
        for (int j = 0; j < 4; j++) wout[tid + 1024 * j] = wp[j] * invp;
        __syncthreads();
    }
}

// ---------------- output epilogue ----------------
__global__ void out_act_kernel(const float* __restrict__ b_out, float* __restrict__ out) {
    int b = blockIdx.x, j = threadIdx.x;  // 256 threads
    float v = b_out[j];
#pragma unroll
    for (int sl = 0; sl < 6; sl++)
        v += g_op[((size_t)sl * BB + b) * 256 + j];
    out[(size_t)b * 256 + j] = 1.f / (1.f + expf(-v));
}

// ---------------- launch ----------------
extern "C" void kernel_launch(void* const* d_in, const int* in_sizes, int n_in,
                              void* d_out, int out_size) {
    const float* in_data      = (const float*)d_in[0];
    const float* memory       = (const float*)d_in[1];
    const float* h_prev       = (const float*)d_in[2];
    const float* c_prev       = (const float*)d_in[3];
    const float* prev_reads   = (const float*)d_in[4];
    const float* prev_weights = (const float*)d_in[5];
    const float* W_ih  = (const float*)d_in[6];
    const float* b_ih  = (const float*)d_in[7];
    const float* W_hh  = (const float*)d_in[8];
    const float* b_hh  = (const float*)d_in[9];
    const float* W_out = (const float*)d_in[10];
    const float* b_out = (const float*)d_in[11];
    const float* Wk    = (const float*)d_in[12];
    const float* bk    = (const float*)d_in[13];
    const float* Wbeta = (const float*)d_in[14];
    const float* bbeta = (const float*)d_in[15];
    const float* Wg    = (const float*)d_in[16];
    const float* bg    = (const float*)d_in[17];
    const float* Ws    = (const float*)d_in[18];
    const float* bs    = (const float*)d_in[19];
    const float* Wgam  = (const float*)d_in[20];
    const float* bgam  = (const float*)d_in[21];
    const float* We    = (const float*)d_in[22];
    const float* be    = (const float*)d_in[23];
    const float* Wa    = (const float*)d_in[24];
    const float* ba    = (const float*)d_in[25];
    float* out = (float*)d_out;

    float* gp; cudaGetSymbolAddress((void**)&gp, g_gp);
    float* pp; cudaGetSymbolAddress((void**)&pp, g_pp);
    float* op; cudaGetSymbolAddress((void**)&op, g_op);
    float* gx; cudaGetSymbolAddress((void**)&gx, g_x);
    float* gc; cudaGetSymbolAddress((void**)&gc, g_c);
    float* ghr; cudaGetSymbolAddress((void**)&ghr, g_hr);
    float* gWstk; cudaGetSymbolAddress((void**)&gWstk, g_Wstk);

    cudaFuncSetAttribute(pass_fused<0>, cudaFuncAttributeMaxDynamicSharedMemorySize, PASS_SMEM);
    cudaFuncSetAttribute(pass_fused<1>, cudaFuncAttributeMaxDynamicSharedMemorySize, PASS_SMEM);
    cudaFuncSetAttribute(pass_fused<2>, cudaFuncAttributeMaxDynamicSharedMemorySize, PASS_SMEM);
    cudaFuncSetAttribute(pass_fused<3>, cudaFuncAttributeMaxDynamicSharedMemorySize, PASS_SMEM);
    cudaFuncSetAttribute(pass_fused<4>, cudaFuncAttributeMaxDynamicSharedMemorySize, PASS_SMEM);

    // 1. pack x + stacked head weights (one kernel)
    pack_all_kernel<<<(BB * 512 + PR * 512 + 255) / 256, 256>>>(
        in_data, prev_reads, Wk, We, Wa, Ws, Wbeta, Wg, Wgam);

    // 2. LSTM gates: x@W_ih^T (slots 0..7) + h@W_hh^T (slots 8..15)
    gemm_tn<<<dim3(32, 2, 8), 256>>>(gx, W_ih, gp, 2048, 512, 64, 0);
    gemm_tn<<<dim3(32, 2, 8), 256>>>(h_prev, W_hh, gp, 2048, 512, 64, 8);
    lstm_act_kernel<<<(BB * 512 + 255) / 256, 256>>>(b_ih, b_hh, c_prev);

    // 3. head-param GEMM + activations
    gemm_tn<<<dim3(25, 2, 8), 256>>>(gc, gWstk, pp, PR, 512, 64, 0);
    param_act_kernel<<<dim3(8, BB), 64>>>(bk, be, ba, bs, bbeta, bg, bgam);

    // 4. fused memory passes (pass + weight in one kernel, 1 block per batch)
    pass_fused<0><<<BB, 1024, PASS_SMEM>>>(memory, prev_weights);
    pass_fused<1><<<BB, 1024, PASS_SMEM>>>(memory, prev_weights);
    pass_fused<2><<<BB, 1024, PASS_SMEM>>>(memory, prev_weights);
    pass_fused<3><<<BB, 1024, PASS_SMEM>>>(memory, prev_weights);
    pass_fused<4><<<BB, 1024, PASS_SMEM>>>(memory, prev_weights);

    // 5. output layer
    gemm_tn<<<dim3(4, 2, 6), 256>>>(ghr, W_out, op, 256, 768, 128, 0);
    out_act_kernel<<<BB, 256>>>(b_out, out);
}

// round 6
// speedup vs baseline: 1.3691x; 1.0614x over previous
#include <cuda_runtime.h>
#include <cuda_fp16.h>
#include <math.h>

#define BB 128
#define NN 4096
#define MM 64
#define HH 512
#define PR 1584   // stacked: 512 Wk + 512 We + 512 Wa + 24 Ws + 8 Wbeta + 8 Wg + 8 Wgam

// ---------------- scratch (device globals; no allocations) ----------------
__device__ float g_x[BB * 512];
__device__ float g_c[BB * HH];
__device__ float g_hr[BB * 768];           // [h(512) | read0..3 (4*64)]
__device__ float g_Wstk[PR * 512];
__device__ float g_gp[16 * BB * 2048];     // gates GEMM split-K partials
__device__ float g_pp[8 * BB * PR];        // head-param GEMM partials
__device__ float g_op[6 * BB * 256];       // output GEMM partials
__device__ float g_keyv[8 * BB * MM];
__device__ float g_keynorm[8 * BB];
__device__ float g_ev[8 * BB * MM];
__device__ float g_av[8 * BB * MM];
__device__ float g_beta[8 * BB];
__device__ float g_gv[8 * BB];
__device__ float g_gamma[8 * BB];
__device__ float g_sv[8 * BB * 3];
__device__ __half g_memh[(size_t)BB * NN * MM];  // fp16 cache of original memory

__device__ __forceinline__ float sigf(float x) { return 1.f / (1.f + __expf(-x)); }
__device__ __forceinline__ float softplusf(float x) {
    return fmaxf(x, 0.f) + log1pf(expf(-fabsf(x)));
}

// ---------------- combined pack kernel ----------------
__global__ void pack_all_kernel(const float* __restrict__ in_data,
                                const float* __restrict__ prev_reads,
                                const float* __restrict__ Wk, const float* __restrict__ We,
                                const float* __restrict__ Wa, const float* __restrict__ Ws,
                                const float* __restrict__ Wbeta, const float* __restrict__ Wg,
                                const float* __restrict__ Wgam) {
    int idx = blockIdx.x * blockDim.x + threadIdx.x;
    if (idx < BB * 512) {
        int b = idx >> 9, c = idx & 511;
        float v;
        if (c < 256) v = in_data[b * 256 + c];
        else {
            int k = c - 256, i = k >> 6, m = k & 63;
            v = prev_reads[((size_t)i * BB + b) * MM + m];
        }
        g_x[idx] = v;
        return;
    }
    int j = idx - BB * 512;
    if (j >= PR * 512) return;
    int r = j >> 9, k = j & 511;
    float v;
    if (r < 512)        v = Wk[(size_t)r * 512 + k];
    else if (r < 1024)  v = We[(size_t)(r - 512) * 512 + k];
    else if (r < 1536)  v = Wa[(size_t)(r - 1024) * 512 + k];
    else if (r < 1560)  v = Ws[(size_t)(r - 1536) * 512 + k];
    else if (r < 1568)  v = Wbeta[(size_t)(r - 1560) * 512 + k];
    else if (r < 1576)  v = Wg[(size_t)(r - 1568) * 512 + k];
    else                v = Wgam[(size_t)(r - 1576) * 512 + k];
    g_Wstk[j] = v;
}

// ---------------- split-K SGEMM body ----------------
__device__ __forceinline__ void gemm_body(
    const float* __restrict__ A, const float* __restrict__ W,
    float* __restrict__ Cp, int R, int K, int kChunk, int kStart, int slot,
    int mBase, int rBase)
{
    __shared__ __align__(16) float As[16][68];
    __shared__ __align__(16) float Bs[16][68];
    const int t = threadIdx.x;
    const int tx = t & 15, ty = t >> 4;
    const int loadRow = t >> 2;
    const int loadK = (t & 3) * 4;
    const float* Arow = A + (size_t)(mBase + loadRow) * K;
    const bool wv = (rBase + loadRow) < R;
    const float* Wrow = W + (size_t)(wv ? (rBase + loadRow) : 0) * K;
    float acc[4][4] = {};
    for (int k0 = kStart; k0 < kStart + kChunk; k0 += 16) {
        float4 a4 = *reinterpret_cast<const float4*>(Arow + k0 + loadK);
        float4 w4 = *reinterpret_cast<const float4*>(Wrow + k0 + loadK);
        if (!wv) w4 = make_float4(0.f, 0.f, 0.f, 0.f);
        __syncthreads();
        As[loadK + 0][loadRow] = a4.x; As[loadK + 1][loadRow] = a4.y;
        As[loadK + 2][loadRow] = a4.z; As[loadK + 3][loadRow] = a4.w;
        Bs[loadK + 0][loadRow] = w4.x; Bs[loadK + 1][loadRow] = w4.y;
        Bs[loadK + 2][loadRow] = w4.z; Bs[loadK + 3][loadRow] = w4.w;
        __syncthreads();
#pragma unroll
        for (int kk = 0; kk < 16; kk++) {
            float4 av = *reinterpret_cast<const float4*>(&As[kk][ty * 4]);
            float4 wvv = *reinterpret_cast<const float4*>(&Bs[kk][tx * 4]);
            float aa[4] = {av.x, av.y, av.z, av.w};
            float ww[4] = {wvv.x, wvv.y, wvv.z, wvv.w};
#pragma unroll
            for (int i = 0; i < 4; i++)
#pragma unroll
                for (int j = 0; j < 4; j++)
                    acc[i][j] = fmaf(aa[i], ww[j], acc[i][j]);
        }
    }
#pragma unroll
    for (int i = 0; i < 4; i++) {
        int m = mBase + ty * 4 + i;
#pragma unroll
        for (int j = 0; j < 4; j++) {
            int r = rBase + tx * 4 + j;
            if (r < R) Cp[((size_t)slot * BB + m) * R + r] = acc[i][j];
        }
    }
}

__global__ __launch_bounds__(256) void gemm_tn(
    const float* __restrict__ A, const float* __restrict__ W,
    float* __restrict__ Cp, int R, int K, int kChunk, int slotBase)
{
    gemm_body(A, W, Cp, R, K, kChunk, blockIdx.z * kChunk, slotBase + blockIdx.z,
              blockIdx.y * 64, blockIdx.x * 64);
}

// both gates GEMMs in one launch: z<8 -> x@W_ih^T (slots 0..7), z>=8 -> h@W_hh^T (slots 8..15)
__global__ __launch_bounds__(256) void gemm_gates(
    const float* __restrict__ A0, const float* __restrict__ W0,
    const float* __restrict__ A1, const float* __restrict__ W1,
    float* __restrict__ Cp)
{
    const int z = blockIdx.z;
    const float* A = (z < 8) ? A0 : A1;
    const float* W = (z < 8) ? W0 : W1;
    gemm_body(A, W, Cp, 2048, 512, 64, (z & 7) * 64, z, blockIdx.y * 64, blockIdx.x * 64);
}

// ---------------- LSTM epilogue (float4 vectorized) ----------------
__global__ void lstm_act_kernel(const float* __restrict__ b_ih, const float* __restrict__ b_hh,
                                const float* __restrict__ c_prev) {
    int idx = blockIdx.x * blockDim.x + threadIdx.x;   // BB*128 threads
    if (idx >= BB * 128) return;
    int b = idx >> 7, j4 = (idx & 127) * 4;
    float4 s[4];
#pragma unroll
    for (int q = 0; q < 4; q++) {
        int col = q * 512 + j4;
        float4 bi = *reinterpret_cast<const float4*>(b_ih + col);
        float4 bh = *reinterpret_cast<const float4*>(b_hh + col);
        s[q] = make_float4(bi.x + bh.x, bi.y + bh.y, bi.z + bh.z, bi.w + bh.w);
    }
#pragma unroll
    for (int sl = 0; sl < 16; sl++) {
        const float* base = g_gp + ((size_t)sl * BB + b) * 2048;
#pragma unroll
        for (int q = 0; q < 4; q++) {
            float4 p = *reinterpret_cast<const float4*>(base + q * 512 + j4);
            s[q].x += p.x; s[q].y += p.y; s[q].z += p.z; s[q].w += p.w;
        }
    }
    float4 cp = *reinterpret_cast<const float4*>(c_prev + b * 512 + j4);
    float cc0 = sigf(s[1].x) * cp.x + sigf(s[0].x) * tanhf(s[2].x);
    float cc1 = sigf(s[1].y) * cp.y + sigf(s[0].y) * tanhf(s[2].y);
    float cc2 = sigf(s[1].z) * cp.z + sigf(s[0].z) * tanhf(s[2].z);
    float cc3 = sigf(s[1].w) * cp.w + sigf(s[0].w) * tanhf(s[2].w);
    *reinterpret_cast<float4*>(g_c + b * 512 + j4) = make_float4(cc0, cc1, cc2, cc3);
    float4 hh = make_float4(sigf(s[3].x) * tanhf(cc0), sigf(s[3].y) * tanhf(cc1),
                            sigf(s[3].z) * tanhf(cc2), sigf(s[3].w) * tanhf(cc3));
    *reinterpret_cast<float4*>(g_hr + (size_t)b * 768 + j4) = hh;
}

// ---------------- head-param epilogue ----------------
__global__ void param_act_kernel(const float* __restrict__ bk, const float* __restrict__ be,
                                 const float* __restrict__ ba, const float* __restrict__ bs,
                                 const float* __restrict__ bbeta, const float* __restrict__ bg,
                                 const float* __restrict__ bgam) {
    int head = blockIdx.x, b = blockIdx.y, t = threadIdx.x;  // 64 threads
    auto val = [&](int r) {
        float s = 0.f;
#pragma unroll
        for (int sl = 0; sl < 8; sl++) s += g_pp[((size_t)sl * BB + b) * PR + r];
        return s;
    };
    int hb = head * BB + b;

    float kv = val(head * 64 + t) + bk[head * 64 + t];
    g_keyv[(size_t)hb * 64 + t] = kv;
    __shared__ float sh2[2];
    __shared__ float s3sh[3];
    float ns = kv * kv;
#pragma unroll
    for (int off = 16; off >= 1; off >>= 1) ns += __shfl_xor_sync(0xffffffffu, ns, off);
    if ((t & 31) == 0) sh2[t >> 5] = ns;

    g_ev[(size_t)hb * 64 + t] = sigf(val(512 + head * 64 + t) + be[head * 64 + t]);
    g_av[(size_t)hb * 64 + t] = tanhf(val(1024 + head * 64 + t) + ba[head * 64 + t]);
    if (t < 3) s3sh[t] = val(1536 + head * 3 + t) + bs[head * 3 + t];
    __syncthreads();
    if (t == 0) g_keynorm[hb] = sqrtf(sh2[0] + sh2[1]);
    if (t < 3) {
        float m = fmaxf(s3sh[0], fmaxf(s3sh[1], s3sh[2]));
        float d = expf(s3sh[0] - m) + expf(s3sh[1] - m) + expf(s3sh[2] - m);
        g_sv[(size_t)hb * 3 + t] = expf(s3sh[t] - m) / d;
    }
    if (t == 0) {
        g_beta[hb]  = softplusf(val(1560 + head) + bbeta[head]);
        g_gv[hb]    = sigf(val(1568 + head) + bg[head]);
        g_gamma[hb] = 1.f + softplusf(val(1576 + head) + bgam[head]);
    }
}

// ---------------- mega pass kernel: all 5 passes, one block per batch ----------------
__device__ __forceinline__ void upd_row(float4& v, float w, const float4& e, const float4& a) {
    v.x = fmaf(w, fmaf(-e.x, v.x, a.x), v.x);
    v.y = fmaf(w, fmaf(-e.y, v.y, a.y), v.y);
    v.z = fmaf(w, fmaf(-e.z, v.z, a.z), v.z);
    v.w = fmaf(w, fmaf(-e.w, v.w, a.w), v.w);
}

__device__ __forceinline__ float blk_reduce32(float v, float* red, bool isMax) {
    int lane = threadIdx.x & 31, wid = threadIdx.x >> 5;
#pragma unroll
    for (int off = 16; off >= 1; off >>= 1) {
        float o = __shfl_xor_sync(0xffffffffu, v, off);
        v = isMax ? fmaxf(v, o) : (v + o);
    }
    if (lane == 0) red[wid] = v;
    __syncthreads();
    if (wid == 0) {
        float x = red[lane];
#pragma unroll
        for (int off = 16; off >= 1; off >>= 1) {
            float o = __shfl_xor_sync(0xffffffffu, x, off);
            x = isMax ? fmaxf(x, o) : (x + o);
        }
        if (lane == 0) red[0] = x;
    }
    __syncthreads();
    float r = red[0];
    __syncthreads();
    return r;
}

// smem layout (floats): simA 4096 | simB 4096 | wg 4096 | wr 4096 | w1 4096 | w3 4096 | w5 4096 | red 32
#define MEGA_SMEM ((7 * 4096 + 32) * 4)

// ST=0: fp32 load + fp16 store; sims h0,h1; weights h0->wr, h1->w1.
// ST=1: read h0 (wr), post-upd w1; sims h2,h3; weights h2->wr, h3->w3.
// ST=2: upd w1, read h2 (wr), post-upd w3; sims h4,h5; weights h4->wr, h5->w5.
// ST=3: upd w1,w3, read h4 (wr), post-upd w5; sim h6; weight h6->wr.
// ST=4: upd w1,w3,w5, read h6 (wr).
template <int ST>
__device__ void pass_body(const float* __restrict__ mem,
                          const float* __restrict__ prev_weights, int b,
                          float* s_simA, float* s_simB, float* s_wg, float* s_red,
                          float* s_wr, float* s_w1, float* s_w3, float* s_w5)
{
    constexpr bool HAS_READ = (ST >= 1);
    constexpr int READ_HEAD = (ST == 1) ? 0 : (ST == 2) ? 2 : (ST == 3) ? 4 : 6;
    constexpr int RIDX = READ_HEAD / 2;
    constexpr bool HAS_POST = (ST >= 1 && ST <= 3);
    constexpr int NSIM = (ST <= 2) ? 2 : (ST == 3) ? 1 : 0;
    constexpr int SH0 = 2 * ST;

    const int tid = threadIdx.x;
    const int lane = tid & 31;
    const int warpId = tid >> 5;
    const int li = lane & 15;
    const int half = lane >> 4;
    const int m4 = li * 4;

    auto ldvec = [&](const float* base, int head) -> float4 {
        return *reinterpret_cast<const float4*>(base + ((size_t)head * BB + b) * 64 + m4);
    };

    float4 e1, a1, e3, a3, e5, a5, k0v, k1v;
    float kn0 = 0.f, kn1 = 0.f;
    if (ST >= 1) { e1 = ldvec(g_ev, 1); a1 = ldvec(g_av, 1); }
    if (ST >= 2) { e3 = ldvec(g_ev, 3); a3 = ldvec(g_av, 3); }
    if (ST >= 3) { e5 = ldvec(g_ev, 5); a5 = ldvec(g_av, 5); }
    if (NSIM >= 1) { k0v = ldvec(g_keyv, SH0); kn0 = g_keynorm[SH0 * BB + b]; }
    if (NSIM >= 2) { k1v = ldvec(g_keyv, SH0 + 1); kn1 = g_keynorm[(SH0 + 1) * BB + b]; }

    float r0 = 0.f, r1 = 0.f, r2 = 0.f, r3 = 0.f;
    const size_t bn = (size_t)b * NN;
    const int rowInBlk = warpId * 2 + half;  // 0..63

    // ---- phase A: stream memory rows ----
#pragma unroll 4
    for (int it = 0; it < 64; it++) {
        const int n = it * 64 + rowInBlk;
        const size_t eidx = (bn + n) * 64 + m4;
        float4 v;
        if (ST == 0) {
            v = __ldcs(reinterpret_cast<const float4*>(mem + eidx));
            __half2 p0 = __floats2half2_rn(v.x, v.y);
            __half2 p1 = __floats2half2_rn(v.z, v.w);
            uint2 st;
            st.x = *reinterpret_cast<unsigned*>(&p0);
            st.y = *reinterpret_cast<unsigned*>(&p1);
            *reinterpret_cast<uint2*>(g_memh + eidx) = st;
        } else {
            uint2 u = __ldg(reinterpret_cast<const uint2*>(g_memh + eidx));
            float2 f0 = __half22float2(*reinterpret_cast<__half2*>(&u.x));
            float2 f1 = __half22float2(*reinterpret_cast<__half2*>(&u.y));
            v = make_float4(f0.x, f0.y, f1.x, f1.y);
        }
        if (ST >= 2) upd_row(v, s_w1[n], e1, a1);
        if (ST >= 3) upd_row(v, s_w3[n], e3, a3);
        if (ST == 4) upd_row(v, s_w5[n], e5, a5);
        if (HAS_READ) {
            float wr = s_wr[n];
            r0 = fmaf(wr, v.x, r0); r1 = fmaf(wr, v.y, r1);
            r2 = fmaf(wr, v.z, r2); r3 = fmaf(wr, v.w, r3);
        }
        if (HAS_POST) {
            if (ST == 1) upd_row(v, s_w1[n], e1, a1);
            else if (ST == 2) upd_row(v, s_w3[n], e3, a3);
            else upd_row(v, s_w5[n], e5, a5);
        }
        if (NSIM >= 1) {
            float ns = v.x * v.x + v.y * v.y + v.z * v.z + v.w * v.w;
            float d0 = v.x * k0v.x + v.y * k0v.y + v.z * k0v.z + v.w * k0v.w;
            float d1 = 0.f;
            if (NSIM >= 2) d1 = v.x * k1v.x + v.y * k1v.y + v.z * k1v.z + v.w * k1v.w;
#pragma unroll
            for (int off = 8; off >= 1; off >>= 1) {
                ns += __shfl_xor_sync(0xffffffffu, ns, off);
                d0 += __shfl_xor_sync(0xffffffffu, d0, off);
                if (NSIM >= 2) d1 += __shfl_xor_sync(0xffffffffu, d1, off);
            }
            if (li == 0) {
                float nm = sqrtf(ns);
                s_simA[n] = d0 / (nm * kn0 + 1e-8f);
                if (NSIM >= 2) s_simB[n] = d1 / (nm * kn1 + 1e-8f);
            }
        }
    }

    // ---- in-block read reduction -> g_hr ----
    if (HAS_READ) {
        __syncthreads();   // s_wg free (phase B of prev pass done)
        r0 += __shfl_down_sync(0xffffffffu, r0, 16);
        r1 += __shfl_down_sync(0xffffffffu, r1, 16);
        r2 += __shfl_down_sync(0xffffffffu, r2, 16);
        r3 += __shfl_down_sync(0xffffffffu, r3, 16);
        if (lane < 16) {
            s_wg[warpId * 64 + m4 + 0] = r0; s_wg[warpId * 64 + m4 + 1] = r1;
            s_wg[warpId * 64 + m4 + 2] = r2; s_wg[warpId * 64 + m4 + 3] = r3;
        }
        __syncthreads();
        if (tid < 64) {
            float s = 0.f;
#pragma unroll
            for (int w = 0; w < 32; w++) s += s_wg[w * 64 + tid];
            g_hr[(size_t)b * 768 + 512 + RIDX * 64 + tid] = s;
        }
    }
    __syncthreads();

    // ---- phase B: weights for freshly computed sims ----
#pragma unroll
    for (int hh = 0; hh < NSIM; hh++) {
        const int head = SH0 + hh;
        const int hb = head * BB + b;
        const float* sim = hh ? s_simB : s_simA;
        float* dest = (hh == 0) ? s_wr : (ST == 0 ? s_w1 : ST == 1 ? s_w3 : s_w5);
        const float* pw = prev_weights + (size_t)hb * NN;
        const float beta = g_beta[hb], gg = g_gv[hb], gamma = g_gamma[hb];
        const float s0 = g_sv[(size_t)hb * 3 + 0];
        const float s1 = g_sv[(size_t)hb * 3 + 1];
        const float s2 = g_sv[(size_t)hb * 3 + 2];
        const int tid2 = threadIdx.x;

        float tv[4];
        float mx = -1e30f;
#pragma unroll
        for (int j = 0; j < 4; j++) {
            tv[j] = beta * sim[tid2 + 1024 * j];
            mx = fmaxf(mx, tv[j]);
        }
        mx = blk_reduce32(mx, s_red, true);
        float se = 0.f, evv[4];
#pragma unroll
        for (int j = 0; j < 4; j++) { evv[j] = __expf(tv[j] - mx); se += evv[j]; }
        se = blk_reduce32(se, s_red, false);
        const float inv = 1.f / se;
#pragma unroll
        for (int j = 0; j < 4; j++) {
            int n = tid2 + 1024 * j;
            s_wg[n] = gg * (evv[j] * inv) + (1.f - gg) * pw[n];
        }
        __syncthreads();
        float sp = 0.f, wp[4];
#pragma unroll
        for (int j = 0; j < 4; j++) {
            int n = tid2 + 1024 * j;
            float ws = s0 * s_wg[(n + 1) & (NN - 1)] + s1 * s_wg[n] + s2 * s_wg[(n - 1) & (NN - 1)];
            float p = __powf(ws, gamma);
            wp[j] = p; sp += p;
        }
        sp = blk_reduce32(sp, s_red, false);
        const float invp = 1.f / (sp + 1e-8f);
#pragma unroll
        for (int j = 0; j < 4; j++) dest[tid2 + 1024 * j] = wp[j] * invp;
        __syncthreads();
    }
}

__global__ __launch_bounds__(1024, 1) void mega_pass(const float* __restrict__ mem,
                                                     const float* __restrict__ prev_weights) {
    extern __shared__ float smem[];
    float* s_simA = smem;
    float* s_simB = smem + 4096;
    float* s_wg   = smem + 8192;
    float* s_wr   = smem + 12288;
    float* s_w1   = smem + 16384;
    float* s_w3   = smem + 20480;
    float* s_w5   = smem + 24576;
    float* s_red  = smem + 28672;
    const int b = blockIdx.x;

    pass_body<0>(mem, prev_weights, b, s_simA, s_simB, s_wg, s_red, s_wr, s_w1, s_w3, s_w5);
    __syncthreads();
    pass_body<1>(mem, prev_weights, b, s_simA, s_simB, s_wg, s_red, s_wr, s_w1, s_w3, s_w5);
    __syncthreads();
    pass_body<2>(mem, prev_weights, b, s_simA, s_simB, s_wg, s_red, s_wr, s_w1, s_w3, s_w5);
    __syncthreads();
    pass_body<3>(mem, prev_weights, b, s_simA, s_simB, s_wg, s_red, s_wr, s_w1, s_w3, s_w5);
    __syncthreads();
    pass_body<4>(mem, prev_weights, b, s_simA, s_simB, s_wg, s_red, s_wr, s_w1, s_w3, s_w5);
}

// ---------------- output epilogue ----------------
__global__ void out_act_kernel(const float* __restrict__ b_out, float* __restrict__ out) {
    int b = blockIdx.x, j = threadIdx.x;  // 256 threads
    float v = b_out[j];
#pragma unroll
    for (int sl = 0; sl < 6; sl++)
        v += g_op[((size_t)sl * BB + b) * 256 + j];
    out[(size_t)b * 256 + j] = 1.f / (1.f + expf(-v));
}

// ---------------- launch ----------------
extern "C" void kernel_launch(void* const* d_in, const int* in_sizes, int n_in,
                              void* d_out, int out_size) {
    const float* in_data      = (const float*)d_in[0];
    const float* memory       = (const float*)d_in[1];
    const float* h_prev       = (const float*)d_in[2];
    const float* c_prev       = (const float*)d_in[3];
    const float* prev_reads   = (const float*)d_in[4];
    const float* prev_weights = (const float*)d_in[5];
    const float* W_ih  = (const float*)d_in[6];
    const float* b_ih  = (const float*)d_in[7];
    const float* W_hh  = (const float*)d_in[8];
    const float* b_hh  = (const float*)d_in[9];
    const float* W_out = (const float*)d_in[10];
    const float* b_out = (const float*)d_in[11];
    const float* Wk    = (const float*)d_in[12];
    const float* bk    = (const float*)d_in[13];
    const float* Wbeta = (const float*)d_in[14];
    const float* bbeta = (const float*)d_in[15];
    const float* Wg    = (const float*)d_in[16];
    const float* bg    = (const float*)d_in[17];
    const float* Ws    = (const float*)d_in[18];
    const float* bs    = (const float*)d_in[19];
    const float* Wgam  = (const float*)d_in[20];
    const float* bgam  = (const float*)d_in[21];
    const float* We    = (const float*)d_in[22];
    const float* be    = (const float*)d_in[23];
    const float* Wa    = (const float*)d_in[24];
    const float* ba    = (const float*)d_in[25];
    float* out = (float*)d_out;

    float* gp; cudaGetSymbolAddress((void**)&gp, g_gp);
    float* pp; cudaGetSymbolAddress((void**)&pp, g_pp);
    float* op; cudaGetSymbolAddress((void**)&op, g_op);
    float* gx; cudaGetSymbolAddress((void**)&gx, g_x);
    float* gc; cudaGetSymbolAddress((void**)&gc, g_c);
    float* ghr; cudaGetSymbolAddress((void**)&ghr, g_hr);
    float* gWstk; cudaGetSymbolAddress((void**)&gWstk, g_Wstk);

    cudaFuncSetAttribute(mega_pass, cudaFuncAttributeMaxDynamicSharedMemorySize, MEGA_SMEM);

    // 1. pack x + stacked head weights
    pack_all_kernel<<<(BB * 512 + PR * 512 + 255) / 256, 256>>>(
        in_data, prev_reads, Wk, We, Wa, Ws, Wbeta, Wg, Wgam);

    // 2. LSTM gates (both GEMMs in one launch) + activation
    gemm_gates<<<dim3(32, 2, 16), 256>>>(gx, W_ih, h_prev, W_hh, gp);
    lstm_act_kernel<<<(BB * 128 + 255) / 256, 256>>>(b_ih, b_hh, c_prev);

    // 3. head-param GEMM + activations
    gemm_tn<<<dim3(25, 2, 8), 256>>>(gc, gWstk, pp, PR, 512, 64, 0);
    param_act_kernel<<<dim3(8, BB), 64>>>(bk, be, ba, bs, bbeta, bg, bgam);

    // 4. all 5 memory passes in ONE kernel (weights live in smem)
    mega_pass<<<BB, 1024, MEGA_SMEM>>>(memory, prev_weights);

    // 5. output layer
    gemm_tn<<<dim3(4, 2, 6), 256>>>(ghr, W_out, op, 256, 768, 128, 0);
    out_act_kernel<<<BB, 256>>>(b_out, out);
}

// round 8
// speedup vs baseline: 1.7703x; 1.2930x over previous
#include <cuda_runtime.h>
#include <cuda_fp16.h>
#include <math.h>

#define BB 128
#define NN 4096
#define MM 64
#define HH 512
#define PR 1584   // stacked: 512 Wk + 512 We + 512 Wa + 24 Ws + 8 Wbeta + 8 Wg + 8 Wgam

// ---------------- scratch (device globals; no allocations) ----------------
__device__ float g_x[BB * 512];
__device__ float g_c[BB * HH];
__device__ float g_hr[BB * 768];           // [h(512) | read0..3 (4*64)]
__device__ float g_Wstk[PR * 512];
__device__ float g_gp[16 * BB * 2048];     // gates GEMM split-K partials
__device__ float g_pp[8 * BB * PR];        // head-param GEMM partials
__device__ float g_op[6 * BB * 256];       // output GEMM partials
__device__ float g_keyv[8 * BB * MM];
__device__ float g_keynorm[8 * BB];
__device__ float g_ev[8 * BB * MM];
__device__ float g_av[8 * BB * MM];
__device__ float g_beta[8 * BB];
__device__ float g_gv[8 * BB];
__device__ float g_gamma[8 * BB];
__device__ float g_sv[8 * BB * 3];
__device__ __half g_memh[(size_t)BB * NN * MM];  // fp16 cache of original memory

__device__ __forceinline__ float sigf(float x) { return 1.f / (1.f + __expf(-x)); }
__device__ __forceinline__ float softplusf(float x) {
    return fmaxf(x, 0.f) + log1pf(expf(-fabsf(x)));
}

// ---------------- combined pack kernel ----------------
__global__ void pack_all_kernel(const float* __restrict__ in_data,
                                const float* __restrict__ prev_reads,
                                const float* __restrict__ Wk, const float* __restrict__ We,
                                const float* __restrict__ Wa, const float* __restrict__ Ws,
                                const float* __restrict__ Wbeta, const float* __restrict__ Wg,
                                const float* __restrict__ Wgam) {
    int idx = blockIdx.x * blockDim.x + threadIdx.x;
    if (idx < BB * 512) {
        int b = idx >> 9, c = idx & 511;
        float v;
        if (c < 256) v = in_data[b * 256 + c];
        else {
            int k = c - 256, i = k >> 6, m = k & 63;
            v = prev_reads[((size_t)i * BB + b) * MM + m];
        }
        g_x[idx] = v;
        return;
    }
    int j = idx - BB * 512;
    if (j >= PR * 512) return;
    int r = j >> 9, k = j & 511;
    float v;
    if (r < 512)        v = Wk[(size_t)r * 512 + k];
    else if (r < 1024)  v = We[(size_t)(r - 512) * 512 + k];
    else if (r < 1536)  v = Wa[(size_t)(r - 1024) * 512 + k];
    else if (r < 1560)  v = Ws[(size_t)(r - 1536) * 512 + k];
    else if (r < 1568)  v = Wbeta[(size_t)(r - 1560) * 512 + k];
    else if (r < 1576)  v = Wg[(size_t)(r - 1568) * 512 + k];
    else                v = Wgam[(size_t)(r - 1576) * 512 + k];
    g_Wstk[j] = v;
}

// ---------------- split-K SGEMM body ----------------
__device__ __forceinline__ void gemm_body(
    const float* __restrict__ A, const float* __restrict__ W,
    float* __restrict__ Cp, int R, int K, int kChunk, int kStart, int slot,
    int mBase, int rBase)
{
    __shared__ __align__(16) float As[16][68];
    __shared__ __align__(16) float Bs[16][68];
    const int t = threadIdx.x;
    const int tx = t & 15, ty = t >> 4;
    const int loadRow = t >> 2;
    const int loadK = (t & 3) * 4;
    const float* Arow = A + (size_t)(mBase + loadRow) * K;
    const bool wv = (rBase + loadRow) < R;
    const float* Wrow = W + (size_t)(wv ? (rBase + loadRow) : 0) * K;
    float acc[4][4] = {};
    for (int k0 = kStart; k0 < kStart + kChunk; k0 += 16) {
        float4 a4 = *reinterpret_cast<const float4*>(Arow + k0 + loadK);
        float4 w4 = *reinterpret_cast<const float4*>(Wrow + k0 + loadK);
        if (!wv) w4 = make_float4(0.f, 0.f, 0.f, 0.f);
        __syncthreads();
        As[loadK + 0][loadRow] = a4.x; As[loadK + 1][loadRow] = a4.y;
        As[loadK + 2][loadRow] = a4.z; As[loadK + 3][loadRow] = a4.w;
        Bs[loadK + 0][loadRow] = w4.x; Bs[loadK + 1][loadRow] = w4.y;
        Bs[loadK + 2][loadRow] = w4.z; Bs[loadK + 3][loadRow] = w4.w;
        __syncthreads();
#pragma unroll
        for (int kk = 0; kk < 16; kk++) {
            float4 av = *reinterpret_cast<const float4*>(&As[kk][ty * 4]);
            float4 wvv = *reinterpret_cast<const float4*>(&Bs[kk][tx * 4]);
            float aa[4] = {av.x, av.y, av.z, av.w};
            float ww[4] = {wvv.x, wvv.y, wvv.z, wvv.w};
#pragma unroll
            for (int i = 0; i < 4; i++)
#pragma unroll
                for (int j = 0; j < 4; j++)
                    acc[i][j] = fmaf(aa[i], ww[j], acc[i][j]);
        }
    }
#pragma unroll
    for (int i = 0; i < 4; i++) {
        int m = mBase + ty * 4 + i;
#pragma unroll
        for (int j = 0; j < 4; j++) {
            int r = rBase + tx * 4 + j;
            if (r < R) Cp[((size_t)slot * BB + m) * R + r] = acc[i][j];
        }
    }
}

__global__ __launch_bounds__(256) void gemm_tn(
    const float* __restrict__ A, const float* __restrict__ W,
    float* __restrict__ Cp, int R, int K, int kChunk, int slotBase)
{
    gemm_body(A, W, Cp, R, K, kChunk, blockIdx.z * kChunk, slotBase + blockIdx.z,
              blockIdx.y * 64, blockIdx.x * 64);
}

// both gates GEMMs in one launch
__global__ __launch_bounds__(256) void gemm_gates(
    const float* __restrict__ A0, const float* __restrict__ W0,
    const float* __restrict__ A1, const float* __restrict__ W1,
    float* __restrict__ Cp)
{
    const int z = blockIdx.z;
    const float* A = (z < 8) ? A0 : A1;
    const float* W = (z < 8) ? W0 : W1;
    gemm_body(A, W, Cp, 2048, 512, 64, (z & 7) * 64, z, blockIdx.y * 64, blockIdx.x * 64);
}

// ---------------- LSTM epilogue (float4 vectorized) ----------------
__global__ void lstm_act_kernel(const float* __restrict__ b_ih, const float* __restrict__ b_hh,
                                const float* __restrict__ c_prev) {
    int idx = blockIdx.x * blockDim.x + threadIdx.x;   // BB*128 threads
    if (idx >= BB * 128) return;
    int b = idx >> 7, j4 = (idx & 127) * 4;
    float4 s[4];
#pragma unroll
    for (int q = 0; q < 4; q++) {
        int col = q * 512 + j4;
        float4 bi = *reinterpret_cast<const float4*>(b_ih + col);
        float4 bh = *reinterpret_cast<const float4*>(b_hh + col);
        s[q] = make_float4(bi.x + bh.x, bi.y + bh.y, bi.z + bh.z, bi.w + bh.w);
    }
#pragma unroll
    for (int sl = 0; sl < 16; sl++) {
        const float* base = g_gp + ((size_t)sl * BB + b) * 2048;
#pragma unroll
        for (int q = 0; q < 4; q++) {
            float4 p = *reinterpret_cast<const float4*>(base + q * 512 + j4);
            s[q].x += p.x; s[q].y += p.y; s[q].z += p.z; s[q].w += p.w;
        }
    }
    float4 cp = *reinterpret_cast<const float4*>(c_prev + b * 512 + j4);
    float cc0 = sigf(s[1].x) * cp.x + sigf(s[0].x) * tanhf(s[2].x);
    float cc1 = sigf(s[1].y) * cp.y + sigf(s[0].y) * tanhf(s[2].y);
    float cc2 = sigf(s[1].z) * cp.z + sigf(s[0].z) * tanhf(s[2].z);
    float cc3 = sigf(s[1].w) * cp.w + sigf(s[0].w) * tanhf(s[2].w);
    *reinterpret_cast<float4*>(g_c + b * 512 + j4) = make_float4(cc0, cc1, cc2, cc3);
    float4 hh = make_float4(sigf(s[3].x) * tanhf(cc0), sigf(s[3].y) * tanhf(cc1),
                            sigf(s[3].z) * tanhf(cc2), sigf(s[3].w) * tanhf(cc3));
    *reinterpret_cast<float4*>(g_hr + (size_t)b * 768 + j4) = hh;
}

// ---------------- head-param epilogue ----------------
__global__ void param_act_kernel(const float* __restrict__ bk, const float* __restrict__ be,
                                 const float* __restrict__ ba, const float* __restrict__ bs,
                                 const float* __restrict__ bbeta, const float* __restrict__ bg,
                                 const float* __restrict__ bgam) {
    int head = blockIdx.x, b = blockIdx.y, t = threadIdx.x;  // 64 threads
    auto val = [&](int r) {
        float s = 0.f;
#pragma unroll
        for (int sl = 0; sl < 8; sl++) s += g_pp[((size_t)sl * BB + b) * PR + r];
        return s;
    };
    int hb = head * BB + b;

    float kv = val(head * 64 + t) + bk[head * 64 + t];
    g_keyv[(size_t)hb * 64 + t] = kv;
    __shared__ float sh2[2];
    __shared__ float s3sh[3];
    float ns = kv * kv;
#pragma unroll
    for (int off = 16; off >= 1; off >>= 1) ns += __shfl_xor_sync(0xffffffffu, ns, off);
    if ((t & 31) == 0) sh2[t >> 5] = ns;

    g_ev[(size_t)hb * 64 + t] = sigf(val(512 + head * 64 + t) + be[head * 64 + t]);
    g_av[(size_t)hb * 64 + t] = tanhf(val(1024 + head * 64 + t) + ba[head * 64 + t]);
    if (t < 3) s3sh[t] = val(1536 + head * 3 + t) + bs[head * 3 + t];
    __syncthreads();
    if (t == 0) g_keynorm[hb] = sqrtf(sh2[0] + sh2[1]);
    if (t < 3) {
        float m = fmaxf(s3sh[0], fmaxf(s3sh[1], s3sh[2]));
        float d = expf(s3sh[0] - m) + expf(s3sh[1] - m) + expf(s3sh[2] - m);
        g_sv[(size_t)hb * 3 + t] = expf(s3sh[t] - m) / d;
    }
    if (t == 0) {
        g_beta[hb]  = softplusf(val(1560 + head) + bbeta[head]);
        g_gv[hb]    = sigf(val(1568 + head) + bg[head]);
        g_gamma[hb] = 1.f + softplusf(val(1576 + head) + bgam[head]);
    }
}

// ---------------- mega pass kernel ----------------
__device__ __forceinline__ float blk_reduce32(float v, float* red, bool isMax) {
    int lane = threadIdx.x & 31, wid = threadIdx.x >> 5;
#pragma unroll
    for (int off = 16; off >= 1; off >>= 1) {
        float o = __shfl_xor_sync(0xffffffffu, v, off);
        v = isMax ? fmaxf(v, o) : (v + o);
    }
    if (lane == 0) red[wid] = v;
    __syncthreads();
    if (wid == 0) {
        float x = red[lane];
#pragma unroll
        for (int off = 16; off >= 1; off >>= 1) {
            float o = __shfl_xor_sync(0xffffffffu, x, off);
            x = isMax ? fmaxf(x, o) : (x + o);
        }
        if (lane == 0) red[0] = x;
    }
    __syncthreads();
    float r = red[0];
    __syncthreads();
    return r;
}

// upd on 4 half2: v += w*(a - e*v)  (ne = -e precomputed)
__device__ __forceinline__ void upd8(__half2* v, __half2 w2,
                                     const __half2* ne, const __half2* a) {
#pragma unroll
    for (int j = 0; j < 4; j++)
        v[j] = __hfma2(w2, __hfma2(ne[j], v[j], a[j]), v[j]);
}

// smem layout (floats): simA 4096 | simB 4096 | wg 4096 | wr 4096 | w1 4096 | w3 4096 | w5 4096 | red 32
#define MEGA_SMEM ((7 * 4096 + 32) * 4)

template <int ST>
__device__ void pass_body(const float* __restrict__ mem,
                          const float* __restrict__ prev_weights, int b,
                          float* s_simA, float* s_simB, float* s_wg, float* s_red,
                          float* s_wr, float* s_w1, float* s_w3, float* s_w5)
{
    constexpr bool HAS_READ = (ST >= 1);
    constexpr int RIDX = (ST - 1);
    constexpr bool HAS_POST = (ST >= 1 && ST <= 3);
    constexpr int NSIM = (ST <= 2) ? 2 : (ST == 3) ? 1 : 0;
    constexpr int SH0 = 2 * ST;

    const int tid = threadIdx.x;
    const int lane = tid & 31;
    const int warpId = tid >> 5;
    const int sub = lane & 7;          // lane within row (8 lanes/row)
    const int rsel = lane >> 3;        // row within warp (4 rows/warp)

    // per-pass head vectors as half2[4] (8 halves per lane at m = sub*8..sub*8+7)
    auto ldh8 = [&](const float* base, int head, __half2* dst, bool neg) {
        const float* p = base + ((size_t)head * BB + b) * 64 + sub * 8;
        float4 f0 = *reinterpret_cast<const float4*>(p);
        float4 f1 = *reinterpret_cast<const float4*>(p + 4);
        dst[0] = __floats2half2_rn(f0.x, f0.y); dst[1] = __floats2half2_rn(f0.z, f0.w);
        dst[2] = __floats2half2_rn(f1.x, f1.y); dst[3] = __floats2half2_rn(f1.z, f1.w);
        if (neg) {
#pragma unroll
            for (int j = 0; j < 4; j++) dst[j] = __hneg2(dst[j]);
        }
    };

    __half2 ne1[4], a1[4], ne3[4], a3[4], ne5[4], a5[4], k0[4], k1[4];
    float kn0 = 0.f, kn1 = 0.f;
    if (ST >= 1) { ldh8(g_ev, 1, ne1, true); ldh8(g_av, 1, a1, false); }
    if (ST >= 2) { ldh8(g_ev, 3, ne3, true); ldh8(g_av, 3, a3, false); }
    if (ST >= 3) { ldh8(g_ev, 5, ne5, true); ldh8(g_av, 5, a5, false); }
    if (NSIM >= 1) { ldh8(g_keyv, SH0, k0, false); kn0 = g_keynorm[SH0 * BB + b]; }
    if (NSIM >= 2) { ldh8(g_keyv, SH0 + 1, k1, false); kn1 = g_keynorm[(SH0 + 1) * BB + b]; }

    float racc[8] = {};
    const size_t bn = (size_t)b * NN;
    const int rowInBlk = warpId * 4 + rsel;  // 0..127

    // ---- phase A: stream memory rows (8 lanes/row, 8 halves/lane) ----
#pragma unroll 4
    for (int it = 0; it < 32; it++) {
        const int n = it * 128 + rowInBlk;
        const size_t hidx = (bn + n) * 64 + sub * 8;
        __half2 v[4];
        if (ST == 0) {
            float4 f0 = __ldcs(reinterpret_cast<const float4*>(mem + hidx));
            float4 f1 = __ldcs(reinterpret_cast<const float4*>(mem + hidx + 4));
            v[0] = __floats2half2_rn(f0.x, f0.y); v[1] = __floats2half2_rn(f0.z, f0.w);
            v[2] = __floats2half2_rn(f1.x, f1.y); v[3] = __floats2half2_rn(f1.z, f1.w);
            *reinterpret_cast<uint4*>(g_memh + hidx) = *reinterpret_cast<uint4*>(v);
        } else {
            uint4 u = __ldg(reinterpret_cast<const uint4*>(g_memh + hidx));
            *reinterpret_cast<uint4*>(v) = u;
        }
        if (ST >= 2) upd8(v, __half2half2(__float2half_rn(s_w1[n])), ne1, a1);
        if (ST >= 3) upd8(v, __half2half2(__float2half_rn(s_w3[n])), ne3, a3);
        if (ST == 4) upd8(v, __half2half2(__float2half_rn(s_w5[n])), ne5, a5);
        if (HAS_READ) {
            float wr = s_wr[n];
#pragma unroll
            for (int j = 0; j < 4; j++) {
                float2 f = __half22float2(v[j]);
                racc[2 * j]     = fmaf(wr, f.x, racc[2 * j]);
                racc[2 * j + 1] = fmaf(wr, f.y, racc[2 * j + 1]);
            }
        }
        if (HAS_POST) {
            if (ST == 1) upd8(v, __half2half2(__float2half_rn(s_w1[n])), ne1, a1);
            else if (ST == 2) upd8(v, __half2half2(__float2half_rn(s_w3[n])), ne3, a3);
            else upd8(v, __half2half2(__float2half_rn(s_w5[n])), ne5, a5);
        }
        if (NSIM >= 1) {
            __half2 ns2 = __floats2half2_rn(0.f, 0.f);
            __half2 d02 = ns2, d12 = ns2;
#pragma unroll
            for (int j = 0; j < 4; j++) {
                ns2 = __hfma2(v[j], v[j], ns2);
                d02 = __hfma2(v[j], k0[j], d02);
                if (NSIM >= 2) d12 = __hfma2(v[j], k1[j], d12);
            }
            float2 nsf = __half22float2(ns2);
            float2 d0f2 = __half22float2(d02);
            float ns = nsf.x + nsf.y;
            float d0 = d0f2.x + d0f2.y;
            float d1 = 0.f;
            if (NSIM >= 2) { float2 t = __half22float2(d12); d1 = t.x + t.y; }
#pragma unroll
            for (int off = 4; off >= 1; off >>= 1) {
                ns += __shfl_xor_sync(0xffffffffu, ns, off);
                d0 += __shfl_xor_sync(0xffffffffu, d0, off);
                if (NSIM >= 2) d1 += __shfl_xor_sync(0xffffffffu, d1, off);
            }
            if (sub == 0) {
                float nm = sqrtf(ns);
                s_simA[n] = d0 / (nm * kn0 + 1e-8f);
                if (NSIM >= 2) s_simB[n] = d1 / (nm * kn1 + 1e-8f);
            }
        }
    }

    // ---- in-block read reduction -> g_hr ----
    if (HAS_READ) {
        __syncthreads();   // s_wg free
#pragma unroll
        for (int j = 0; j < 8; j++) {
            racc[j] += __shfl_down_sync(0xffffffffu, racc[j], 16);
            racc[j] += __shfl_down_sync(0xffffffffu, racc[j], 8);
        }
        if (lane < 8) {
#pragma unroll
            for (int j = 0; j < 8; j++)
                s_wg[warpId * 64 + sub * 8 + j] = racc[j];
        }
        __syncthreads();
        if (tid < 64) {
            float s = 0.f;
#pragma unroll
            for (int w = 0; w < 32; w++) s += s_wg[w * 64 + tid];
            g_hr[(size_t)b * 768 + 512 + RIDX * 64 + tid] = s;
        }
    }
    __syncthreads();

    // ---- phase B: weights for freshly computed sims ----
#pragma unroll
    for (int hh = 0; hh < NSIM; hh++) {
        const int head = SH0 + hh;
        const int hb = head * BB + b;
        const float* sim = hh ? s_simB : s_simA;
        float* dest = (hh == 0) ? s_wr : (ST == 0 ? s_w1 : ST == 1 ? s_w3 : s_w5);
        const float* pw = prev_weights + (size_t)hb * NN;
        const float beta = g_beta[hb], gg = g_gv[hb], gamma = g_gamma[hb];
        const float s0 = g_sv[(size_t)hb * 3 + 0];
        const float s1 = g_sv[(size_t)hb * 3 + 1];
        const float s2 = g_sv[(size_t)hb * 3 + 2];

        float tv[4];
        float mx = -1e30f;
#pragma unroll
        for (int j = 0; j < 4; j++) {
            tv[j] = beta * sim[tid + 1024 * j];
            mx = fmaxf(mx, tv[j]);
        }
        mx = blk_reduce32(mx, s_red, true);
        float se = 0.f, evv[4];
#pragma unroll
        for (int j = 0; j < 4; j++) { evv[j] = __expf(tv[j] - mx); se += evv[j]; }
        se = blk_reduce32(se, s_red, false);
        const float inv = 1.f / se;
#pragma unroll
        for (int j = 0; j < 4; j++) {
            int n = tid + 1024 * j;
            s_wg[n] = gg * (evv[j] * inv) + (1.f - gg) * pw[n];
        }
        __syncthreads();
        float sp = 0.f, wp[4];
#pragma unroll
        for (int j = 0; j < 4; j++) {
            int n = tid + 1024 * j;
            float ws = s0 * s_wg[(n + 1) & (NN - 1)] + s1 * s_wg[n] + s2 * s_wg[(n - 1) & (NN - 1)];
            float p = __powf(ws, gamma);
            wp[j] = p; sp += p;
        }
        sp = blk_reduce32(sp, s_red, false);
        const float invp = 1.f / (sp + 1e-8f);
#pragma unroll
        for (int j = 0; j < 4; j++) dest[tid + 1024 * j] = wp[j] * invp;
        __syncthreads();
    }
}

__global__ __launch_bounds__(1024, 1) void mega_pass(const float* __restrict__ mem,
                                                     const float* __restrict__ prev_weights) {
    extern __shared__ float smem[];
    float* s_simA = smem;
    float* s_simB = smem + 4096;
    float* s_wg   = smem + 8192;
    float* s_wr   = smem + 12288;
    float* s_w1   = smem + 16384;
    float* s_w3   = smem + 20480;
    float* s_w5   = smem + 24576;
    float* s_red  = smem + 28672;
    const int b = blockIdx.x;

    pass_body<0>(mem, prev_weights, b, s_simA, s_simB, s_wg, s_red, s_wr, s_w1, s_w3, s_w5);
    __syncthreads();
    pass_body<1>(mem, prev_weights, b, s_simA, s_simB, s_wg, s_red, s_wr, s_w1, s_w3, s_w5);
    __syncthreads();
    pass_body<2>(mem, prev_weights, b, s_simA, s_simB, s_wg, s_red, s_wr, s_w1, s_w3, s_w5);
    __syncthreads();
    pass_body<3>(mem, prev_weights, b, s_simA, s_simB, s_wg, s_red, s_wr, s_w1, s_w3, s_w5);
    __syncthreads();
    pass_body<4>(mem, prev_weights, b, s_simA, s_simB, s_wg, s_red, s_wr, s_w1, s_w3, s_w5);
}

// ---------------- output epilogue ----------------
__global__ void out_act_kernel(const float* __restrict__ b_out, float* __restrict__ out) {
    int b = blockIdx.x, j = threadIdx.x;  // 256 threads
    float v = b_out[j];
#pragma unroll
    for (int sl = 0; sl < 6; sl++)
        v += g_op[((size_t)sl * BB + b) * 256 + j];
    out[(size_t)b * 256 + j] = 1.f / (1.f + expf(-v));
}

// ---------------- launch ----------------
extern "C" void kernel_launch(void* const* d_in, const int* in_sizes, int n_in,
                              void* d_out, int out_size) {
    const float* in_data      = (const float*)d_in[0];
    const float* memory       = (const float*)d_in[1];
    const float* h_prev       = (const float*)d_in[2];
    const float* c_prev       = (const float*)d_in[3];
    const float* prev_reads   = (const float*)d_in[4];
    const float* prev_weights = (const float*)d_in[5];
    const float* W_ih  = (const float*)d_in[6];
    const float* b_ih  = (const float*)d_in[7];
    const float* W_hh  = (const float*)d_in[8];
    const float* b_hh  = (const float*)d_in[9];
    const float* W_out = (const float*)d_in[10];
    const float* b_out = (const float*)d_in[11];
    const float* Wk    = (const float*)d_in[12];
    const float* bk    = (const float*)d_in[13];
    const float* Wbeta = (const float*)d_in[14];
    const float* bbeta = (const float*)d_in[15];
    const float* Wg    = (const float*)d_in[16];
    const float* bg    = (const float*)d_in[17];
    const float* Ws    = (const float*)d_in[18];
    const float* bs    = (const float*)d_in[19];
    const float* Wgam  = (const float*)d_in[20];
    const float* bgam  = (const float*)d_in[21];
    const float* We    = (const float*)d_in[22];
    const float* be    = (const float*)d_in[23];
    const float* Wa    = (const float*)d_in[24];
    const float* ba    = (const float*)d_in[25];
    float* out = (float*)d_out;

    float* gp; cudaGetSymbolAddress((void**)&gp, g_gp);
    float* pp; cudaGetSymbolAddress((void**)&pp, g_pp);
    float* op; cudaGetSymbolAddress((void**)&op, g_op);
    float* gx; cudaGetSymbolAddress((void**)&gx, g_x);
    float* gc; cudaGetSymbolAddress((void**)&gc, g_c);
    float* ghr; cudaGetSymbolAddress((void**)&ghr, g_hr);
    float* gWstk; cudaGetSymbolAddress((void**)&gWstk, g_Wstk);

    cudaFuncSetAttribute(mega_pass, cudaFuncAttributeMaxDynamicSharedMemorySize, MEGA_SMEM);

    // 1. pack x + stacked head weights
    pack_all_kernel<<<(BB * 512 + PR * 512 + 255) / 256, 256>>>(
        in_data, prev_reads, Wk, We, Wa, Ws, Wbeta, Wg, Wgam);

    // 2. LSTM gates (both GEMMs in one launch) + activation
    gemm_gates<<<dim3(32, 2, 16), 256>>>(gx, W_ih, h_prev, W_hh, gp);
    lstm_act_kernel<<<(BB * 128 + 255) / 256, 256>>>(b_ih, b_hh, c_prev);

    // 3. head-param GEMM + activations
    gemm_tn<<<dim3(25, 2, 8), 256>>>(gc, gWstk, pp, PR, 512, 64, 0);
    param_act_kernel<<<dim3(8, BB), 64>>>(bk, be, ba, bs, bbeta, bg, bgam);

    // 4. all 5 memory passes in ONE kernel (half2 phase A, weights in smem)
    mega_pass<<<BB, 1024, MEGA_SMEM>>>(memory, prev_weights);

    // 5. output layer
    gemm_tn<<<dim3(4, 2, 6), 256>>>(ghr, W_out, op, 256, 768, 128, 0);
    out_act_kernel<<<BB, 256>>>(b_out, out);
}

// round 9
// speedup vs baseline: 1.8384x; 1.0385x over previous
#include <cuda_runtime.h>
#include <cuda_fp16.h>
#include <math.h>

#define BB 128
#define NN 4096
#define MM 64
#define HH 512
#define PR 1584   // stacked: 512 Wk + 512 We + 512 Wa + 24 Ws + 8 Wbeta + 8 Wg + 8 Wgam

// ---------------- scratch (device globals; no allocations) ----------------
__device__ float g_x[BB * 512];
__device__ float g_c[BB * HH];
__device__ float g_hr[BB * 768];           // [h(512) | read0..3 (4*64)]
__device__ float g_Wstk[PR * 512];
__device__ float g_gp[16 * BB * 2048];     // gates GEMM split-K partials
__device__ float g_pp[8 * BB * PR];        // head-param GEMM partials
__device__ float g_op[6 * BB * 256];       // output GEMM partials
__device__ float g_keyv[8 * BB * MM];
__device__ float g_keynorm[8 * BB];
__device__ float g_ev[8 * BB * MM];
__device__ float g_av[8 * BB * MM];
__device__ float g_beta[8 * BB];
__device__ float g_gv[8 * BB];
__device__ float g_gamma[8 * BB];
__device__ float g_sv[8 * BB * 3];
__device__ __half g_memh[(size_t)BB * NN * MM];  // fp16 cache of original memory

__device__ __forceinline__ float sigf(float x) { return 1.f / (1.f + __expf(-x)); }
__device__ __forceinline__ float softplusf(float x) {
    return fmaxf(x, 0.f) + log1pf(expf(-fabsf(x)));
}

// ---------------- combined pack kernel ----------------
__global__ void pack_all_kernel(const float* __restrict__ in_data,
                                const float* __restrict__ prev_reads,
                                const float* __restrict__ Wk, const float* __restrict__ We,
                                const float* __restrict__ Wa, const float* __restrict__ Ws,
                                const float* __restrict__ Wbeta, const float* __restrict__ Wg,
                                const float* __restrict__ Wgam) {
    int idx = blockIdx.x * blockDim.x + threadIdx.x;
    if (idx < BB * 512) {
        int b = idx >> 9, c = idx & 511;
        float v;
        if (c < 256) v = in_data[b * 256 + c];
        else {
            int k = c - 256, i = k >> 6, m = k & 63;
            v = prev_reads[((size_t)i * BB + b) * MM + m];
        }
        g_x[idx] = v;
        return;
    }
    int j = idx - BB * 512;
    if (j >= PR * 512) return;
    int r = j >> 9, k = j & 511;
    float v;
    if (r < 512)        v = Wk[(size_t)r * 512 + k];
    else if (r < 1024)  v = We[(size_t)(r - 512) * 512 + k];
    else if (r < 1536)  v = Wa[(size_t)(r - 1024) * 512 + k];
    else if (r < 1560)  v = Ws[(size_t)(r - 1536) * 512 + k];
    else if (r < 1568)  v = Wbeta[(size_t)(r - 1560) * 512 + k];
    else if (r < 1576)  v = Wg[(size_t)(r - 1568) * 512 + k];
    else                v = Wgam[(size_t)(r - 1576) * 512 + k];
    g_Wstk[j] = v;
}

// ---------------- split-K SGEMM body ----------------
__device__ __forceinline__ void gemm_body(
    const float* __restrict__ A, const float* __restrict__ W,
    float* __restrict__ Cp, int R, int K, int kChunk, int kStart, int slot,
    int mBase, int rBase)
{
    __shared__ __align__(16) float As[16][68];
    __shared__ __align__(16) float Bs[16][68];
    const int t = threadIdx.x;
    const int tx = t & 15, ty = t >> 4;
    const int loadRow = t >> 2;
    const int loadK = (t & 3) * 4;
    const float* Arow = A + (size_t)(mBase + loadRow) * K;
    const bool wv = (rBase + loadRow) < R;
    const float* Wrow = W + (size_t)(wv ? (rBase + loadRow) : 0) * K;
    float acc[4][4] = {};
    for (int k0 = kStart; k0 < kStart + kChunk; k0 += 16) {
        float4 a4 = *reinterpret_cast<const float4*>(Arow + k0 + loadK);
        float4 w4 = *reinterpret_cast<const float4*>(Wrow + k0 + loadK);
        if (!wv) w4 = make_float4(0.f, 0.f, 0.f, 0.f);
        __syncthreads();
        As[loadK + 0][loadRow] = a4.x; As[loadK + 1][loadRow] = a4.y;
        As[loadK + 2][loadRow] = a4.z; As[loadK + 3][loadRow] = a4.w;
        Bs[loadK + 0][loadRow] = w4.x; Bs[loadK + 1][loadRow] = w4.y;
        Bs[loadK + 2][loadRow] = w4.z; Bs[loadK + 3][loadRow] = w4.w;
        __syncthreads();
#pragma unroll
        for (int kk = 0; kk < 16; kk++) {
            float4 av = *reinterpret_cast<const float4*>(&As[kk][ty * 4]);
            float4 wvv = *reinterpret_cast<const float4*>(&Bs[kk][tx * 4]);
            float aa[4] = {av.x, av.y, av.z, av.w};
            float ww[4] = {wvv.x, wvv.y, wvv.z, wvv.w};
#pragma unroll
            for (int i = 0; i < 4; i++)
#pragma unroll
                for (int j = 0; j < 4; j++)
                    acc[i][j] = fmaf(aa[i], ww[j], acc[i][j]);
        }
    }
#pragma unroll
    for (int i = 0; i < 4; i++) {
        int m = mBase + ty * 4 + i;
#pragma unroll
        for (int j = 0; j < 4; j++) {
            int r = rBase + tx * 4 + j;
            if (r < R) Cp[((size_t)slot * BB + m) * R + r] = acc[i][j];
        }
    }
}

__global__ __launch_bounds__(256) void gemm_tn(
    const float* __restrict__ A, const float* __restrict__ W,
    float* __restrict__ Cp, int R, int K, int kChunk, int slotBase)
{
    gemm_body(A, W, Cp, R, K, kChunk, blockIdx.z * kChunk, slotBase + blockIdx.z,
              blockIdx.y * 64, blockIdx.x * 64);
}

// both gates GEMMs in one launch
__global__ __launch_bounds__(256) void gemm_gates(
    const float* __restrict__ A0, const float* __restrict__ W0,
    const float* __restrict__ A1, const float* __restrict__ W1,
    float* __restrict__ Cp)
{
    const int z = blockIdx.z;
    const float* A = (z < 8) ? A0 : A1;
    const float* W = (z < 8) ? W0 : W1;
    gemm_body(A, W, Cp, 2048, 512, 64, (z & 7) * 64, z, blockIdx.y * 64, blockIdx.x * 64);
}

// ---------------- LSTM epilogue (float4 vectorized) ----------------
__global__ void lstm_act_kernel(const float* __restrict__ b_ih, const float* __restrict__ b_hh,
                                const float* __restrict__ c_prev) {
    int idx = blockIdx.x * blockDim.x + threadIdx.x;   // BB*128 threads
    if (idx >= BB * 128) return;
    int b = idx >> 7, j4 = (idx & 127) * 4;
    float4 s[4];
#pragma unroll
    for (int q = 0; q < 4; q++) {
        int col = q * 512 + j4;
        float4 bi = *reinterpret_cast<const float4*>(b_ih + col);
        float4 bh = *reinterpret_cast<const float4*>(b_hh + col);
        s[q] = make_float4(bi.x + bh.x, bi.y + bh.y, bi.z + bh.z, bi.w + bh.w);
    }
#pragma unroll
    for (int sl = 0; sl < 16; sl++) {
        const float* base = g_gp + ((size_t)sl * BB + b) * 2048;
#pragma unroll
        for (int q = 0; q < 4; q++) {
            float4 p = *reinterpret_cast<const float4*>(base + q * 512 + j4);
            s[q].x += p.x; s[q].y += p.y; s[q].z += p.z; s[q].w += p.w;
        }
    }
    float4 cp = *reinterpret_cast<const float4*>(c_prev + b * 512 + j4);
    float cc0 = sigf(s[1].x) * cp.x + sigf(s[0].x) * tanhf(s[2].x);
    float cc1 = sigf(s[1].y) * cp.y + sigf(s[0].y) * tanhf(s[2].y);
    float cc2 = sigf(s[1].z) * cp.z + sigf(s[0].z) * tanhf(s[2].z);
    float cc3 = sigf(s[1].w) * cp.w + sigf(s[0].w) * tanhf(s[2].w);
    *reinterpret_cast<float4*>(g_c + b * 512 + j4) = make_float4(cc0, cc1, cc2, cc3);
    float4 hh = make_float4(sigf(s[3].x) * tanhf(cc0), sigf(s[3].y) * tanhf(cc1),
                            sigf(s[3].z) * tanhf(cc2), sigf(s[3].w) * tanhf(cc3));
    *reinterpret_cast<float4*>(g_hr + (size_t)b * 768 + j4) = hh;
}

// ---------------- head-param epilogue ----------------
__global__ void param_act_kernel(const float* __restrict__ bk, const float* __restrict__ be,
                                 const float* __restrict__ ba, const float* __restrict__ bs,
                                 const float* __restrict__ bbeta, const float* __restrict__ bg,
                                 const float* __restrict__ bgam) {
    int head = blockIdx.x, b = blockIdx.y, t = threadIdx.x;  // 64 threads
    auto val = [&](int r) {
        float s = 0.f;
#pragma unroll
        for (int sl = 0; sl < 8; sl++) s += g_pp[((size_t)sl * BB + b) * PR + r];
        return s;
    };
    int hb = head * BB + b;

    float kv = val(head * 64 + t) + bk[head * 64 + t];
    g_keyv[(size_t)hb * 64 + t] = kv;
    __shared__ float sh2[2];
    __shared__ float s3sh[3];
    float ns = kv * kv;
#pragma unroll
    for (int off = 16; off >= 1; off >>= 1) ns += __shfl_xor_sync(0xffffffffu, ns, off);
    if ((t & 31) == 0) sh2[t >> 5] = ns;

    g_ev[(size_t)hb * 64 + t] = sigf(val(512 + head * 64 + t) + be[head * 64 + t]);
    g_av[(size_t)hb * 64 + t] = tanhf(val(1024 + head * 64 + t) + ba[head * 64 + t]);
    if (t < 3) s3sh[t] = val(1536 + head * 3 + t) + bs[head * 3 + t];
    __syncthreads();
    if (t == 0) g_keynorm[hb] = sqrtf(sh2[0] + sh2[1]);
    if (t < 3) {
        float m = fmaxf(s3sh[0], fmaxf(s3sh[1], s3sh[2]));
        float d = expf(s3sh[0] - m) + expf(s3sh[1] - m) + expf(s3sh[2] - m);
        g_sv[(size_t)hb * 3 + t] = expf(s3sh[t] - m) / d;
    }
    if (t == 0) {
        g_beta[hb]  = softplusf(val(1560 + head) + bbeta[head]);
        g_gv[hb]    = sigf(val(1568 + head) + bg[head]);
        g_gamma[hb] = 1.f + softplusf(val(1576 + head) + bgam[head]);
    }
}

// ---------------- mega pass kernel ----------------
__device__ __forceinline__ float blk_reduce32(float v, float* red, bool isMax) {
    int lane = threadIdx.x & 31, wid = threadIdx.x >> 5;
#pragma unroll
    for (int off = 16; off >= 1; off >>= 1) {
        float o = __shfl_xor_sync(0xffffffffu, v, off);
        v = isMax ? fmaxf(v, o) : (v + o);
    }
    if (lane == 0) red[wid] = v;
    __syncthreads();
    if (wid == 0) {
        float x = red[lane];
#pragma unroll
        for (int off = 16; off >= 1; off >>= 1) {
            float o = __shfl_xor_sync(0xffffffffu, x, off);
            x = isMax ? fmaxf(x, o) : (x + o);
        }
        if (lane == 0) red[0] = x;
    }
    __syncthreads();
    float r = red[0];
    __syncthreads();
    return r;
}

// upd on 4 half2: v += w*(a - e*v)  (ne = -e precomputed)
__device__ __forceinline__ void upd8(__half2* v, __half2 w2,
                                     const __half2* ne, const __half2* a) {
#pragma unroll
    for (int j = 0; j < 4; j++)
        v[j] = __hfma2(w2, __hfma2(ne[j], v[j], a[j]), v[j]);
}

// smem layout (floats): simA 4096 | simB 4096 | wg 4096 | wr 4096 | w1 4096 | w3 4096 | w5 4096 | red 32
#define MEGA_SMEM ((7 * 4096 + 32) * 4)

template <int ST>
__device__ void pass_body(const float* __restrict__ mem,
                          const float* __restrict__ prev_weights, int b,
                          float* s_simA, float* s_simB, float* s_wg, float* s_red,
                          float* s_wr, float* s_w1, float* s_w3, float* s_w5)
{
    constexpr bool HAS_READ = (ST >= 1);
    constexpr int RIDX = (ST - 1);
    constexpr bool HAS_POST = (ST >= 1 && ST <= 3);
    constexpr int NSIM = (ST <= 2) ? 2 : (ST == 3) ? 1 : 0;
    constexpr int SH0 = 2 * ST;

    const int tid = threadIdx.x;
    const int lane = tid & 31;
    const int warpId = tid >> 5;
    const int sub = lane & 7;          // lane within row (8 lanes/row)
    const int rsel = lane >> 3;        // row within warp (4 rows/warp)

    auto ldh8 = [&](const float* base, int head, __half2* dst, bool neg) {
        const float* p = base + ((size_t)head * BB + b) * 64 + sub * 8;
        float4 f0 = *reinterpret_cast<const float4*>(p);
        float4 f1 = *reinterpret_cast<const float4*>(p + 4);
        dst[0] = __floats2half2_rn(f0.x, f0.y); dst[1] = __floats2half2_rn(f0.z, f0.w);
        dst[2] = __floats2half2_rn(f1.x, f1.y); dst[3] = __floats2half2_rn(f1.z, f1.w);
        if (neg) {
#pragma unroll
            for (int j = 0; j < 4; j++) dst[j] = __hneg2(dst[j]);
        }
    };

    __half2 ne1[4], a1[4], ne3[4], a3[4], ne5[4], a5[4], k0[4], k1[4];
    float kn0 = 0.f, kn1 = 0.f;
    if (ST >= 1) { ldh8(g_ev, 1, ne1, true); ldh8(g_av, 1, a1, false); }
    if (ST >= 2) { ldh8(g_ev, 3, ne3, true); ldh8(g_av, 3, a3, false); }
    if (ST >= 3) { ldh8(g_ev, 5, ne5, true); ldh8(g_av, 5, a5, false); }
    if (NSIM >= 1) { ldh8(g_keyv, SH0, k0, false); kn0 = g_keynorm[SH0 * BB + b]; }
    if (NSIM >= 2) { ldh8(g_keyv, SH0 + 1, k1, false); kn1 = g_keynorm[(SH0 + 1) * BB + b]; }

    float racc[8] = {};
    const size_t bn = (size_t)b * NN;
    const int rowInBlk = warpId * 4 + rsel;  // 0..127

    // ---- phase A with software pipelining (prefetch next iter) ----
    uint4 cu = make_uint4(0, 0, 0, 0);
    float4 cf0 = make_float4(0, 0, 0, 0), cf1 = cf0;
    float cw1 = 0.f, cw3 = 0.f, cw5 = 0.f, cwr = 0.f;
    {
        const int n = rowInBlk;
        const size_t hidx = (bn + n) * 64 + sub * 8;
        if (ST == 0) {
            cf0 = __ldcs(reinterpret_cast<const float4*>(mem + hidx));
            cf1 = __ldcs(reinterpret_cast<const float4*>(mem + hidx + 4));
        } else {
            cu = __ldg(reinterpret_cast<const uint4*>(g_memh + hidx));
        }
        if (ST >= 1) { cwr = s_wr[n]; cw1 = s_w1[n]; }
        if (ST >= 2) cw3 = s_w3[n];
        if (ST >= 3) cw5 = s_w5[n];
    }

#pragma unroll 1
    for (int it = 0; it < 32; it++) {
        const int n = it * 128 + rowInBlk;
        // prefetch next iteration
        uint4 nu = make_uint4(0, 0, 0, 0);
        float4 nf0 = make_float4(0, 0, 0, 0), nf1 = nf0;
        float nw1 = 0.f, nw3 = 0.f, nw5 = 0.f, nwr = 0.f;
        if (it < 31) {
            const int n2 = n + 128;
            const size_t hidx2 = (bn + n2) * 64 + sub * 8;
            if (ST == 0) {
                nf0 = __ldcs(reinterpret_cast<const float4*>(mem + hidx2));
                nf1 = __ldcs(reinterpret_cast<const float4*>(mem + hidx2 + 4));
            } else {
                nu = __ldg(reinterpret_cast<const uint4*>(g_memh + hidx2));
            }
            if (ST >= 1) { nwr = s_wr[n2]; nw1 = s_w1[n2]; }
            if (ST >= 2) nw3 = s_w3[n2];
            if (ST >= 3) nw5 = s_w5[n2];
        }
        // compute current
        __half2 v[4];
        if (ST == 0) {
            v[0] = __floats2half2_rn(cf0.x, cf0.y); v[1] = __floats2half2_rn(cf0.z, cf0.w);
            v[2] = __floats2half2_rn(cf1.x, cf1.y); v[3] = __floats2half2_rn(cf1.z, cf1.w);
            const size_t hidx = (bn + n) * 64 + sub * 8;
            *reinterpret_cast<uint4*>(g_memh + hidx) = *reinterpret_cast<uint4*>(v);
        } else {
            *reinterpret_cast<uint4*>(v) = cu;
        }
        if (ST >= 2) upd8(v, __half2half2(__float2half_rn(cw1)), ne1, a1);
        if (ST >= 3) upd8(v, __half2half2(__float2half_rn(cw3)), ne3, a3);
        if (ST == 4) upd8(v, __half2half2(__float2half_rn(cw5)), ne5, a5);
        if (HAS_READ) {
#pragma unroll
            for (int j = 0; j < 4; j++) {
                float2 f = __half22float2(v[j]);
                racc[2 * j]     = fmaf(cwr, f.x, racc[2 * j]);
                racc[2 * j + 1] = fmaf(cwr, f.y, racc[2 * j + 1]);
            }
        }
        if (HAS_POST) {
            float pwv = (ST == 1) ? cw1 : (ST == 2) ? cw3 : cw5;
            const __half2* pne = (ST == 1) ? ne1 : (ST == 2) ? ne3 : ne5;
            const __half2* pa  = (ST == 1) ? a1  : (ST == 2) ? a3  : a5;
            upd8(v, __half2half2(__float2half_rn(pwv)), pne, pa);
        }
        if (NSIM >= 1) {
            __half2 ns2 = __floats2half2_rn(0.f, 0.f);
            __half2 d02 = ns2, d12 = ns2;
#pragma unroll
            for (int j = 0; j < 4; j++) {
                ns2 = __hfma2(v[j], v[j], ns2);
                d02 = __hfma2(v[j], k0[j], d02);
                if (NSIM >= 2) d12 = __hfma2(v[j], k1[j], d12);
            }
            float2 nsf = __half22float2(ns2);
            float2 d0f2 = __half22float2(d02);
            float ns = nsf.x + nsf.y;
            float d0 = d0f2.x + d0f2.y;
            float d1 = 0.f;
            if (NSIM >= 2) { float2 t = __half22float2(d12); d1 = t.x + t.y; }
#pragma unroll
            for (int off = 4; off >= 1; off >>= 1) {
                ns += __shfl_xor_sync(0xffffffffu, ns, off);
                d0 += __shfl_xor_sync(0xffffffffu, d0, off);
                if (NSIM >= 2) d1 += __shfl_xor_sync(0xffffffffu, d1, off);
            }
            if (sub == 0) {
                float nm = sqrtf(ns);
                s_simA[n] = d0 / (nm * kn0 + 1e-8f);
                if (NSIM >= 2) s_simB[n] = d1 / (nm * kn1 + 1e-8f);
            }
        }
        // rotate prefetched -> current
        cu = nu; cf0 = nf0; cf1 = nf1;
        cwr = nwr; cw1 = nw1; cw3 = nw3; cw5 = nw5;
    }

    // ---- in-block read reduction -> g_hr ----
    if (HAS_READ) {
        __syncthreads();   // s_wg free
#pragma unroll
        for (int j = 0; j < 8; j++) {
            racc[j] += __shfl_down_sync(0xffffffffu, racc[j], 16);
            racc[j] += __shfl_down_sync(0xffffffffu, racc[j], 8);
        }
        if (lane < 8) {
#pragma unroll
            for (int j = 0; j < 8; j++)
                s_wg[warpId * 64 + sub * 8 + j] = racc[j];
        }
        __syncthreads();
        if (tid < 64) {
            float s = 0.f;
#pragma unroll
            for (int w = 0; w < 32; w++) s += s_wg[w * 64 + tid];
            g_hr[(size_t)b * 768 + 512 + RIDX * 64 + tid] = s;
        }
    }
    __syncthreads();

    // ---- phase B: weights for freshly computed sims ----
#pragma unroll
    for (int hh = 0; hh < NSIM; hh++) {
        const int head = SH0 + hh;
        const int hb = head * BB + b;
        const float* sim = hh ? s_simB : s_simA;
        float* dest = (hh == 0) ? s_wr : (ST == 0 ? s_w1 : ST == 1 ? s_w3 : s_w5);
        const float* pw = prev_weights + (size_t)hb * NN;
        const float beta = g_beta[hb], gg = g_gv[hb], gamma = g_gamma[hb];
        const float s0 = g_sv[(size_t)hb * 3 + 0];
        const float s1 = g_sv[(size_t)hb * 3 + 1];
        const float s2 = g_sv[(size_t)hb * 3 + 2];

        float tv[4];
        float mx = -1e30f;
#pragma unroll
        for (int j = 0; j < 4; j++) {
            tv[j] = beta * sim[tid + 1024 * j];
            mx = fmaxf(mx, tv[j]);
        }
        mx = blk_reduce32(mx, s_red, true);
        float se = 0.f, evv[4];
#pragma unroll
        for (int j = 0; j < 4; j++) { evv[j] = __expf(tv[j] - mx); se += evv[j]; }
        se = blk_reduce32(se, s_red, false);
        const float inv = 1.f / se;
#pragma unroll
        for (int j = 0; j < 4; j++) {
            int n = tid + 1024 * j;
            s_wg[n] = gg * (evv[j] * inv) + (1.f - gg) * pw[n];
        }
        __syncthreads();
        float sp = 0.f, wp[4];
#pragma unroll
        for (int j = 0; j < 4; j++) {
            int n = tid + 1024 * j;
            float ws = s0 * s_wg[(n + 1) & (NN - 1)] + s1 * s_wg[n] + s2 * s_wg[(n - 1) & (NN - 1)];
            float p = __powf(ws, gamma);
            wp[j] = p; sp += p;
        }
        sp = blk_reduce32(sp, s_red, false);
        const float invp = 1.f / (sp + 1e-8f);
#pragma unroll
        for (int j = 0; j < 4; j++) dest[tid + 1024 * j] = wp[j] * invp;
        __syncthreads();
    }
}

__global__ __launch_bounds__(1024, 1) void mega_pass(const float* __restrict__ mem,
                                                     const float* __restrict__ prev_weights) {
    extern __shared__ float smem[];
    float* s_simA = smem;
    float* s_simB = smem + 4096;
    float* s_wg   = smem + 8192;
    float* s_wr   = smem + 12288;
    float* s_w1   = smem + 16384;
    float* s_w3   = smem + 20480;
    float* s_w5   = smem + 24576;
    float* s_red  = smem + 28672;
    const int b = blockIdx.x;

    pass_body<0>(mem, prev_weights, b, s_simA, s_simB, s_wg, s_red, s_wr, s_w1, s_w3, s_w5);
    __syncthreads();
    pass_body<1>(mem, prev_weights, b, s_simA, s_simB, s_wg, s_red, s_wr, s_w1, s_w3, s_w5);
    __syncthreads();
    pass_body<2>(mem, prev_weights, b, s_simA, s_simB, s_wg, s_red, s_wr, s_w1, s_w3, s_w5);
    __syncthreads();
    pass_body<3>(mem, prev_weights, b, s_simA, s_simB, s_wg, s_red, s_wr, s_w1, s_w3, s_w5);
    __syncthreads();
    pass_body<4>(mem, prev_weights, b, s_simA, s_simB, s_wg, s_red, s_wr, s_w1, s_w3, s_w5);
}

// ---------------- output epilogue ----------------
__global__ void out_act_kernel(const float* __restrict__ b_out, float* __restrict__ out) {
    int b = blockIdx.x, j = threadIdx.x;  // 256 threads
    float v = b_out[j];
#pragma unroll
    for (int sl = 0; sl < 6; sl++)
        v += g_op[((size_t)sl * BB + b) * 256 + j];
    out[(size_t)b * 256 + j] = 1.f / (1.f + expf(-v));
}

// ---------------- launch ----------------
extern "C" void kernel_launch(void* const* d_in, const int* in_sizes, int n_in,
                              void* d_out, int out_size) {
    const float* in_data      = (const float*)d_in[0];
    const float* memory       = (const float*)d_in[1];
    const float* h_prev       = (const float*)d_in[2];
    const float* c_prev       = (const float*)d_in[3];
    const float* prev_reads   = (const float*)d_in[4];
    const float* prev_weights = (const float*)d_in[5];
    const float* W_ih  = (const float*)d_in[6];
    const float* b_ih  = (const float*)d_in[7];
    const float* W_hh  = (const float*)d_in[8];
    const float* b_hh  = (const float*)d_in[9];
    const float* W_out = (const float*)d_in[10];
    const float* b_out = (const float*)d_in[11];
    const float* Wk    = (const float*)d_in[12];
    const float* bk    = (const float*)d_in[13];
    const float* Wbeta = (const float*)d_in[14];
    const float* bbeta = (const float*)d_in[15];
    const float* Wg    = (const float*)d_in[16];
    const float* bg    = (const float*)d_in[17];
    const float* Ws    = (const float*)d_in[18];
    const float* bs    = (const float*)d_in[19];
    const float* Wgam  = (const float*)d_in[20];
    const float* bgam  = (const float*)d_in[21];
    const float* We    = (const float*)d_in[22];
    const float* be    = (const float*)d_in[23];
    const float* Wa    = (const float*)d_in[24];
    const float* ba    = (const float*)d_in[25];
    float* out = (float*)d_out;

    float* gp; cudaGetSymbolAddress((void**)&gp, g_gp);
    float* pp; cudaGetSymbolAddress((void**)&pp, g_pp);
    float* op; cudaGetSymbolAddress((void**)&op, g_op);
    float* gx; cudaGetSymbolAddress((void**)&gx, g_x);
    float* gc; cudaGetSymbolAddress((void**)&gc, g_c);
    float* ghr; cudaGetSymbolAddress((void**)&ghr, g_hr);
    float* gWstk; cudaGetSymbolAddress((void**)&gWstk, g_Wstk);

    cudaFuncSetAttribute(mega_pass, cudaFuncAttributeMaxDynamicSharedMemorySize, MEGA_SMEM);

    // 1. pack x + stacked head weights
    pack_all_kernel<<<(BB * 512 + PR * 512 + 255) / 256, 256>>>(
        in_data, prev_reads, Wk, We, Wa, Ws, Wbeta, Wg, Wgam);

    // 2. LSTM gates (both GEMMs in one launch) + activation
    gemm_gates<<<dim3(32, 2, 16), 256>>>(gx, W_ih, h_prev, W_hh, gp);
    lstm_act_kernel<<<(BB * 128 + 255) / 256, 256>>>(b_ih, b_hh, c_prev);

    // 3. head-param GEMM + activations
    gemm_tn<<<dim3(25, 2, 8), 256>>>(gc, gWstk, pp, PR, 512, 64, 0);
    param_act_kernel<<<dim3(8, BB), 64>>>(bk, be, ba, bs, bbeta, bg, bgam);

    // 4. all 5 memory passes in ONE kernel (pipelined phase A)
    mega_pass<<<BB, 1024, MEGA_SMEM>>>(memory, prev_weights);

    // 5. output layer
    gemm_tn<<<dim3(4, 2, 6), 256>>>(ghr, W_out, op, 256, 768, 128, 0);
    out_act_kernel<<<BB, 256>>>(b_out, out);
}

// round 10
// speedup vs baseline: 1.8629x; 1.0133x over previous
#include <cuda_runtime.h>
#include <cuda_fp16.h>
#include <math.h>

#define BB 128
#define NN 4096
#define MM 64
#define HH 512
#define PR 1584   // stacked: 512 Wk + 512 We + 512 Wa + 24 Ws + 8 Wbeta + 8 Wg + 8 Wgam

// ---------------- scratch (device globals; no allocations) ----------------
__device__ float g_x[BB * 512];
__device__ float g_c[BB * HH];
__device__ float g_hr[BB * 768];           // [h(512) | read0..3 (4*64)]
__device__ float g_Wstk[PR * 512];
__device__ float g_gp[8 * BB * 2048];      // gates GEMM split-K partials
__device__ float g_pp[4 * BB * PR];        // head-param GEMM partials
__device__ float g_op[6 * BB * 256];       // output GEMM partials
__device__ float g_keyv[8 * BB * MM];
__device__ float g_keynorm[8 * BB];
__device__ float g_ev[8 * BB * MM];
__device__ float g_av[8 * BB * MM];
__device__ float g_beta[8 * BB];
__device__ float g_gv[8 * BB];
__device__ float g_gamma[8 * BB];
__device__ float g_sv[8 * BB * 3];
__device__ __half g_memh[(size_t)BB * NN * MM];  // fp16 cache of original memory

__device__ __forceinline__ float sigf(float x) { return 1.f / (1.f + __expf(-x)); }
__device__ __forceinline__ float softplusf(float x) {
    return fmaxf(x, 0.f) + log1pf(expf(-fabsf(x)));
}

// ---------------- combined pack kernel ----------------
__global__ void pack_all_kernel(const float* __restrict__ in_data,
                                const float* __restrict__ prev_reads,
                                const float* __restrict__ Wk, const float* __restrict__ We,
                                const float* __restrict__ Wa, const float* __restrict__ Ws,
                                const float* __restrict__ Wbeta, const float* __restrict__ Wg,
                                const float* __restrict__ Wgam) {
    int idx = blockIdx.x * blockDim.x + threadIdx.x;
    if (idx < BB * 512) {
        int b = idx >> 9, c = idx & 511;
        float v;
        if (c < 256) v = in_data[b * 256 + c];
        else {
            int k = c - 256, i = k >> 6, m = k & 63;
            v = prev_reads[((size_t)i * BB + b) * MM + m];
        }
        g_x[idx] = v;
        return;
    }
    int j = idx - BB * 512;
    if (j >= PR * 512) return;
    int r = j >> 9, k = j & 511;
    float v;
    if (r < 512)        v = Wk[(size_t)r * 512 + k];
    else if (r < 1024)  v = We[(size_t)(r - 512) * 512 + k];
    else if (r < 1536)  v = Wa[(size_t)(r - 1024) * 512 + k];
    else if (r < 1560)  v = Ws[(size_t)(r - 1536) * 512 + k];
    else if (r < 1568)  v = Wbeta[(size_t)(r - 1560) * 512 + k];
    else if (r < 1576)  v = Wg[(size_t)(r - 1568) * 512 + k];
    else                v = Wgam[(size_t)(r - 1576) * 512 + k];
    g_Wstk[j] = v;
}

// ---------------- split-K SGEMM body ----------------
__device__ __forceinline__ void gemm_body(
    const float* __restrict__ A, const float* __restrict__ W,
    float* __restrict__ Cp, int R, int K, int kChunk, int kStart, int slot,
    int mBase, int rBase)
{
    __shared__ __align__(16) float As[16][68];
    __shared__ __align__(16) float Bs[16][68];
    const int t = threadIdx.x;
    const int tx = t & 15, ty = t >> 4;
    const int loadRow = t >> 2;
    const int loadK = (t & 3) * 4;
    const float* Arow = A + (size_t)(mBase + loadRow) * K;
    const bool wv = (rBase + loadRow) < R;
    const float* Wrow = W + (size_t)(wv ? (rBase + loadRow) : 0) * K;
    float acc[4][4] = {};
    for (int k0 = kStart; k0 < kStart + kChunk; k0 += 16) {
        float4 a4 = *reinterpret_cast<const float4*>(Arow + k0 + loadK);
        float4 w4 = *reinterpret_cast<const float4*>(Wrow + k0 + loadK);
        if (!wv) w4 = make_float4(0.f, 0.f, 0.f, 0.f);
        __syncthreads();
        As[loadK + 0][loadRow] = a4.x; As[loadK + 1][loadRow] = a4.y;
        As[loadK + 2][loadRow] = a4.z; As[loadK + 3][loadRow] = a4.w;
        Bs[loadK + 0][loadRow] = w4.x; Bs[loadK + 1][loadRow] = w4.y;
        Bs[loadK + 2][loadRow] = w4.z; Bs[loadK + 3][loadRow] = w4.w;
        __syncthreads();
#pragma unroll
        for (int kk = 0; kk < 16; kk++) {
            float4 av = *reinterpret_cast<const float4*>(&As[kk][ty * 4]);
            float4 wvv = *reinterpret_cast<const float4*>(&Bs[kk][tx * 4]);
            float aa[4] = {av.x, av.y, av.z, av.w};
            float ww[4] = {wvv.x, wvv.y, wvv.z, wvv.w};
#pragma unroll
            for (int i = 0; i < 4; i++)
#pragma unroll
                for (int j = 0; j < 4; j++)
                    acc[i][j] = fmaf(aa[i], ww[j], acc[i][j]);
        }
    }
#pragma unroll
    for (int i = 0; i < 4; i++) {
        int m = mBase + ty * 4 + i;
#pragma unroll
        for (int j = 0; j < 4; j++) {
            int r = rBase + tx * 4 + j;
            if (r < R) Cp[((size_t)slot * BB + m) * R + r] = acc[i][j];
        }
    }
}

__global__ __launch_bounds__(256) void gemm_tn(
    const float* __restrict__ A, const float* __restrict__ W,
    float* __restrict__ Cp, int R, int K, int kChunk, int slotBase)
{
    gemm_body(A, W, Cp, R, K, kChunk, blockIdx.z * kChunk, slotBase + blockIdx.z,
              blockIdx.y * 64, blockIdx.x * 64);
}

// both gates GEMMs in one launch: z<4 -> x@W_ih^T (slots 0..3), z>=4 -> h@W_hh^T (slots 4..7)
__global__ __launch_bounds__(256) void gemm_gates(
    const float* __restrict__ A0, const float* __restrict__ W0,
    const float* __restrict__ A1, const float* __restrict__ W1,
    float* __restrict__ Cp)
{
    const int z = blockIdx.z;
    const float* A = (z < 4) ? A0 : A1;
    const float* W = (z < 4) ? W0 : W1;
    gemm_body(A, W, Cp, 2048, 512, 128, (z & 3) * 128, z, blockIdx.y * 64, blockIdx.x * 64);
}

// ---------------- LSTM epilogue (float4 vectorized) ----------------
__global__ void lstm_act_kernel(const float* __restrict__ b_ih, const float* __restrict__ b_hh,
                                const float* __restrict__ c_prev) {
    int idx = blockIdx.x * blockDim.x + threadIdx.x;   // BB*128 threads
    if (idx >= BB * 128) return;
    int b = idx >> 7, j4 = (idx & 127) * 4;
    float4 s[4];
#pragma unroll
    for (int q = 0; q < 4; q++) {
        int col = q * 512 + j4;
        float4 bi = *reinterpret_cast<const float4*>(b_ih + col);
        float4 bh = *reinterpret_cast<const float4*>(b_hh + col);
        s[q] = make_float4(bi.x + bh.x, bi.y + bh.y, bi.z + bh.z, bi.w + bh.w);
    }
#pragma unroll
    for (int sl = 0; sl < 8; sl++) {
        const float* base = g_gp + ((size_t)sl * BB + b) * 2048;
#pragma unroll
        for (int q = 0; q < 4; q++) {
            float4 p = *reinterpret_cast<const float4*>(base + q * 512 + j4);
            s[q].x += p.x; s[q].y += p.y; s[q].z += p.z; s[q].w += p.w;
        }
    }
    float4 cp = *reinterpret_cast<const float4*>(c_prev + b * 512 + j4);
    float cc0 = sigf(s[1].x) * cp.x + sigf(s[0].x) * tanhf(s[2].x);
    float cc1 = sigf(s[1].y) * cp.y + sigf(s[0].y) * tanhf(s[2].y);
    float cc2 = sigf(s[1].z) * cp.z + sigf(s[0].z) * tanhf(s[2].z);
    float cc3 = sigf(s[1].w) * cp.w + sigf(s[0].w) * tanhf(s[2].w);
    *reinterpret_cast<float4*>(g_c + b * 512 + j4) = make_float4(cc0, cc1, cc2, cc3);
    float4 hh = make_float4(sigf(s[3].x) * tanhf(cc0), sigf(s[3].y) * tanhf(cc1),
                            sigf(s[3].z) * tanhf(cc2), sigf(s[3].w) * tanhf(cc3));
    *reinterpret_cast<float4*>(g_hr + (size_t)b * 768 + j4) = hh;
}

// ---------------- head-param epilogue ----------------
__global__ void param_act_kernel(const float* __restrict__ bk, const float* __restrict__ be,
                                 const float* __restrict__ ba, const float* __restrict__ bs,
                                 const float* __restrict__ bbeta, const float* __restrict__ bg,
                                 const float* __restrict__ bgam) {
    int head = blockIdx.x, b = blockIdx.y, t = threadIdx.x;  // 64 threads
    auto val = [&](int r) {
        float s = 0.f;
#pragma unroll
        for (int sl = 0; sl < 4; sl++) s += g_pp[((size_t)sl * BB + b) * PR + r];
        return s;
    };
    int hb = head * BB + b;

    float kv = val(head * 64 + t) + bk[head * 64 + t];
    g_keyv[(size_t)hb * 64 + t] = kv;
    __shared__ float sh2[2];
    __shared__ float s3sh[3];
    float ns = kv * kv;
#pragma unroll
    for (int off = 16; off >= 1; off >>= 1) ns += __shfl_xor_sync(0xffffffffu, ns, off);
    if ((t & 31) == 0) sh2[t >> 5] = ns;

    g_ev[(size_t)hb * 64 + t] = sigf(val(512 + head * 64 + t) + be[head * 64 + t]);
    g_av[(size_t)hb * 64 + t] = tanhf(val(1024 + head * 64 + t) + ba[head * 64 + t]);
    if (t < 3) s3sh[t] = val(1536 + head * 3 + t) + bs[head * 3 + t];
    __syncthreads();
    if (t == 0) g_keynorm[hb] = sqrtf(sh2[0] + sh2[1]);
    if (t < 3) {
        float m = fmaxf(s3sh[0], fmaxf(s3sh[1], s3sh[2]));
        float d = expf(s3sh[0] - m) + expf(s3sh[1] - m) + expf(s3sh[2] - m);
        g_sv[(size_t)hb * 3 + t] = expf(s3sh[t] - m) / d;
    }
    if (t == 0) {
        g_beta[hb]  = softplusf(val(1560 + head) + bbeta[head]);
        g_gv[hb]    = sigf(val(1568 + head) + bg[head]);
        g_gamma[hb] = 1.f + softplusf(val(1576 + head) + bgam[head]);
    }
}

// ---------------- mega pass kernel ----------------
// float2 block reduction (both heads at once), 3 barriers total
__device__ __forceinline__ float2 blk_reduce_f2(float2 v, float2* red) {
    int lane = threadIdx.x & 31, wid = threadIdx.x >> 5;
#pragma unroll
    for (int off = 16; off >= 1; off >>= 1) {
        v.x += __shfl_xor_sync(0xffffffffu, v.x, off);
        v.y += __shfl_xor_sync(0xffffffffu, v.y, off);
    }
    if (lane == 0) red[wid] = v;
    __syncthreads();
    if (wid == 0) {
        float2 x = red[lane];
#pragma unroll
        for (int off = 16; off >= 1; off >>= 1) {
            x.x += __shfl_xor_sync(0xffffffffu, x.x, off);
            x.y += __shfl_xor_sync(0xffffffffu, x.y, off);
        }
        if (lane == 0) red[0] = x;
    }
    __syncthreads();
    float2 r = red[0];
    __syncthreads();
    return r;
}

// upd on 4 half2: v += w*(a - e*v)  (ne = -e precomputed)
__device__ __forceinline__ void upd8(__half2* v, __half2 w2,
                                     const __half2* ne, const __half2* a) {
#pragma unroll
    for (int j = 0; j < 4; j++)
        v[j] = __hfma2(w2, __hfma2(ne[j], v[j], a[j]), v[j]);
}

// smem layout (floats): simA 4096 | simB 4096 | wg 4096 | wr 4096 | w1 4096 | w3 4096 | w5 4096 | red 64
#define MEGA_SMEM ((7 * 4096 + 64) * 4)

template <int ST>
__device__ void pass_body(const float* __restrict__ mem,
                          const float* __restrict__ prev_weights, int b,
                          float* s_simA, float* s_simB, float* s_wg, float2* s_red,
                          float* s_wr, float* s_w1, float* s_w3, float* s_w5)
{
    constexpr bool HAS_READ = (ST >= 1);
    constexpr int RIDX = (ST - 1);
    constexpr bool HAS_POST = (ST >= 1 && ST <= 3);
    constexpr int NSIM = (ST <= 2) ? 2 : (ST == 3) ? 1 : 0;
    constexpr int SH0 = 2 * ST;

    const int tid = threadIdx.x;
    const int lane = tid & 31;
    const int warpId = tid >> 5;
    const int sub = lane & 7;          // lane within row (8 lanes/row)
    const int rsel = lane >> 3;        // row within warp (4 rows/warp)

    auto ldh8 = [&](const float* base, int head, __half2* dst, bool neg) {
        const float* p = base + ((size_t)head * BB + b) * 64 + sub * 8;
        float4 f0 = *reinterpret_cast<const float4*>(p);
        float4 f1 = *reinterpret_cast<const float4*>(p + 4);
        dst[0] = __floats2half2_rn(f0.x, f0.y); dst[1] = __floats2half2_rn(f0.z, f0.w);
        dst[2] = __floats2half2_rn(f1.x, f1.y); dst[3] = __floats2half2_rn(f1.z, f1.w);
        if (neg) {
#pragma unroll
            for (int j = 0; j < 4; j++) dst[j] = __hneg2(dst[j]);
        }
    };

    __half2 ne1[4], a1[4], ne3[4], a3[4], ne5[4], a5[4], k0[4], k1[4];
    float kn0 = 0.f, kn1 = 0.f;
    if (ST >= 1) { ldh8(g_ev, 1, ne1, true); ldh8(g_av, 1, a1, false); }
    if (ST >= 2) { ldh8(g_ev, 3, ne3, true); ldh8(g_av, 3, a3, false); }
    if (ST >= 3) { ldh8(g_ev, 5, ne5, true); ldh8(g_av, 5, a5, false); }
    if (NSIM >= 1) { ldh8(g_keyv, SH0, k0, false); kn0 = g_keynorm[SH0 * BB + b]; }
    if (NSIM >= 2) { ldh8(g_keyv, SH0 + 1, k1, false); kn1 = g_keynorm[(SH0 + 1) * BB + b]; }

    float racc[8] = {};
    const size_t bn = (size_t)b * NN;
    const int rowInBlk = warpId * 4 + rsel;  // 0..127

    // ---- phase A with software pipelining (prefetch next iter) ----
    uint4 cu = make_uint4(0, 0, 0, 0);
    float4 cf0 = make_float4(0, 0, 0, 0), cf1 = cf0;
    float cw1 = 0.f, cw3 = 0.f, cw5 = 0.f, cwr = 0.f;
    {
        const int n = rowInBlk;
        const size_t hidx = (bn + n) * 64 + sub * 8;
        if (ST == 0) {
            cf0 = __ldcs(reinterpret_cast<const float4*>(mem + hidx));
            cf1 = __ldcs(reinterpret_cast<const float4*>(mem + hidx + 4));
        } else {
            cu = __ldg(reinterpret_cast<const uint4*>(g_memh + hidx));
        }
        if (ST >= 1) { cwr = s_wr[n]; cw1 = s_w1[n]; }
        if (ST >= 2) cw3 = s_w3[n];
        if (ST >= 3) cw5 = s_w5[n];
    }

#pragma unroll 1
    for (int it = 0; it < 32; it++) {
        const int n = it * 128 + rowInBlk;
        // prefetch next iteration
        uint4 nu = make_uint4(0, 0, 0, 0);
        float4 nf0 = make_float4(0, 0, 0, 0), nf1 = nf0;
        float nw1 = 0.f, nw3 = 0.f, nw5 = 0.f, nwr = 0.f;
        if (it < 31) {
            const int n2 = n + 128;
            const size_t hidx2 = (bn + n2) * 64 + sub * 8;
            if (ST == 0) {
                nf0 = __ldcs(reinterpret_cast<const float4*>(mem + hidx2));
                nf1 = __ldcs(reinterpret_cast<const float4*>(mem + hidx2 + 4));
            } else {
                nu = __ldg(reinterpret_cast<const uint4*>(g_memh + hidx2));
            }
            if (ST >= 1) { nwr = s_wr[n2]; nw1 = s_w1[n2]; }
            if (ST >= 2) nw3 = s_w3[n2];
            if (ST >= 3) nw5 = s_w5[n2];
        }
        // compute current
        __half2 v[4];
        if (ST == 0) {
            v[0] = __floats2half2_rn(cf0.x, cf0.y); v[1] = __floats2half2_rn(cf0.z, cf0.w);
            v[2] = __floats2half2_rn(cf1.x, cf1.y); v[3] = __floats2half2_rn(cf1.z, cf1.w);
            const size_t hidx = (bn + n) * 64 + sub * 8;
            *reinterpret_cast<uint4*>(g_memh + hidx) = *reinterpret_cast<uint4*>(v);
        } else {
            *reinterpret_cast<uint4*>(v) = cu;
        }
        if (ST >= 2) upd8(v, __half2half2(__float2half_rn(cw1)), ne1, a1);
        if (ST >= 3) upd8(v, __half2half2(__float2half_rn(cw3)), ne3, a3);
        if (ST == 4) upd8(v, __half2half2(__float2half_rn(cw5)), ne5, a5);
        if (HAS_READ) {
#pragma unroll
            for (int j = 0; j < 4; j++) {
                float2 f = __half22float2(v[j]);
                racc[2 * j]     = fmaf(cwr, f.x, racc[2 * j]);
                racc[2 * j + 1] = fmaf(cwr, f.y, racc[2 * j + 1]);
            }
        }
        if (HAS_POST) {
            float pwv = (ST == 1) ? cw1 : (ST == 2) ? cw3 : cw5;
            const __half2* pne = (ST == 1) ? ne1 : (ST == 2) ? ne3 : ne5;
            const __half2* pa  = (ST == 1) ? a1  : (ST == 2) ? a3  : a5;
            upd8(v, __half2half2(__float2half_rn(pwv)), pne, pa);
        }
        if (NSIM >= 1) {
            __half2 ns2 = __floats2half2_rn(0.f, 0.f);
            __half2 d02 = ns2, d12 = ns2;
#pragma unroll
            for (int j = 0; j < 4; j++) {
                ns2 = __hfma2(v[j], v[j], ns2);
                d02 = __hfma2(v[j], k0[j], d02);
                if (NSIM >= 2) d12 = __hfma2(v[j], k1[j], d12);
            }
            float2 nsf = __half22float2(ns2);
            float2 d0f2 = __half22float2(d02);
            float ns = nsf.x + nsf.y;
            float d0 = d0f2.x + d0f2.y;
            float d1 = 0.f;
            if (NSIM >= 2) { float2 t = __half22float2(d12); d1 = t.x + t.y; }
#pragma unroll
            for (int off = 4; off >= 1; off >>= 1) {
                ns += __shfl_xor_sync(0xffffffffu, ns, off);
                d0 += __shfl_xor_sync(0xffffffffu, d0, off);
                if (NSIM >= 2) d1 += __shfl_xor_sync(0xffffffffu, d1, off);
            }
            if (sub == 0) {
                float nm = sqrtf(ns);
                s_simA[n] = d0 / (nm * kn0 + 1e-8f);
                if (NSIM >= 2) s_simB[n] = d1 / (nm * kn1 + 1e-8f);
            }
        }
        // rotate prefetched -> current
        cu = nu; cf0 = nf0; cf1 = nf1;
        cwr = nwr; cw1 = nw1; cw3 = nw3; cw5 = nw5;
    }

    // ---- in-block read reduction -> g_hr ----
    if (HAS_READ) {
        __syncthreads();   // s_wg free
#pragma unroll
        for (int j = 0; j < 8; j++) {
            racc[j] += __shfl_down_sync(0xffffffffu, racc[j], 16);
            racc[j] += __shfl_down_sync(0xffffffffu, racc[j], 8);
        }
        if (lane < 8) {
#pragma unroll
            for (int j = 0; j < 8; j++)
                s_wg[warpId * 64 + sub * 8 + j] = racc[j];
        }
        __syncthreads();
        if (tid < 64) {
            float s = 0.f;
#pragma unroll
            for (int w = 0; w < 32; w++) s += s_wg[w * 64 + tid];
            g_hr[(size_t)b * 768 + 512 + RIDX * 64 + tid] = s;
        }
    }
    __syncthreads();

    // ---- phase B: weights for freshly computed sims (both heads fused) ----
    if (NSIM >= 1) {
        const int hbA = SH0 * BB + b;
        const int hbB = (SH0 + 1) * BB + b;
        float* destA = s_wr;
        float* destB = (ST == 0) ? s_w1 : (ST == 1) ? s_w3 : s_w5;
        const float* pwA = prev_weights + (size_t)hbA * NN;
        const float* pwB = prev_weights + (size_t)hbB * NN;
        const float betaA = g_beta[hbA], ggA = g_gv[hbA], gamA = g_gamma[hbA];
        const float sA0 = g_sv[(size_t)hbA * 3 + 0];
        const float sA1 = g_sv[(size_t)hbA * 3 + 1];
        const float sA2 = g_sv[(size_t)hbA * 3 + 2];
        float betaB = 0.f, ggB = 0.f, gamB = 1.f, sB0 = 0.f, sB1 = 0.f, sB2 = 0.f;
        if (NSIM >= 2) {
            betaB = g_beta[hbB]; ggB = g_gv[hbB]; gamB = g_gamma[hbB];
            sB0 = g_sv[(size_t)hbB * 3 + 0];
            sB1 = g_sv[(size_t)hbB * 3 + 1];
            sB2 = g_sv[(size_t)hbB * 3 + 2];
        }

        // exp (no max-subtract: |beta*sim| bounded) + sum, both heads in one reduce
        float exA[4], exB[4];
        float2 se = make_float2(0.f, 0.f);
#pragma unroll
        for (int j = 0; j < 4; j++) {
            int n = tid + 1024 * j;
            exA[j] = __expf(betaA * s_simA[n]); se.x += exA[j];
            if (NSIM >= 2) { exB[j] = __expf(betaB * s_simB[n]); se.y += exB[j]; }
        }
        se = blk_reduce_f2(se, s_red);
        const float invA = 1.f / se.x;
        const float invB = (NSIM >= 2) ? 1.f / se.y : 0.f;
        // interpolate with prev weights, write wg in place of sims
#pragma unroll
        for (int j = 0; j < 4; j++) {
            int n = tid + 1024 * j;
            s_simA[n] = ggA * (exA[j] * invA) + (1.f - ggA) * pwA[n];
            if (NSIM >= 2) s_simB[n] = ggB * (exB[j] * invB) + (1.f - ggB) * pwB[n];
        }
        __syncthreads();
        // shift + sharpen, both heads in one reduce
        float pA[4], pB[4];
        float2 sp = make_float2(0.f, 0.f);
#pragma unroll
        for (int j = 0; j < 4; j++) {
            int n = tid + 1024 * j;
            int np = (n + 1) & (NN - 1), nm = (n - 1) & (NN - 1);
            float wsA = sA0 * s_simA[np] + sA1 * s_simA[n] + sA2 * s_simA[nm];
            pA[j] = __powf(wsA, gamA); sp.x += pA[j];
            if (NSIM >= 2) {
                float wsB = sB0 * s_simB[np] + sB1 * s_simB[n] + sB2 * s_simB[nm];
                pB[j] = __powf(wsB, gamB); sp.y += pB[j];
            }
        }
        sp = blk_reduce_f2(sp, s_red);
        const float invpA = 1.f / (sp.x + 1e-8f);
        const float invpB = (NSIM >= 2) ? 1.f / (sp.y + 1e-8f) : 0.f;
#pragma unroll
        for (int j = 0; j < 4; j++) {
            int n = tid + 1024 * j;
            destA[n] = pA[j] * invpA;
            if (NSIM >= 2) destB[n] = pB[j] * invpB;
        }
        __syncthreads();
    }
}

__global__ __launch_bounds__(1024, 1) void mega_pass(const float* __restrict__ mem,
                                                     const float* __restrict__ prev_weights) {
    extern __shared__ float smem[];
    float* s_simA = smem;
    float* s_simB = smem + 4096;
    float* s_wg   = smem + 8192;
    float* s_wr   = smem + 12288;
    float* s_w1   = smem + 16384;
    float* s_w3   = smem + 20480;
    float* s_w5   = smem + 24576;
    float2* s_red = reinterpret_cast<float2*>(smem + 28672);
    const int b = blockIdx.x;

    pass_body<0>(mem, prev_weights, b, s_simA, s_simB, s_wg, s_red, s_wr, s_w1, s_w3, s_w5);
    __syncthreads();
    pass_body<1>(mem, prev_weights, b, s_simA, s_simB, s_wg, s_red, s_wr, s_w1, s_w3, s_w5);
    __syncthreads();
    pass_body<2>(mem, prev_weights, b, s_simA, s_simB, s_wg, s_red, s_wr, s_w1, s_w3, s_w5);
    __syncthreads();
    pass_body<3>(mem, prev_weights, b, s_simA, s_simB, s_wg, s_red, s_wr, s_w1, s_w3, s_w5);
    __syncthreads();
    pass_body<4>(mem, prev_weights, b, s_simA, s_simB, s_wg, s_red, s_wr, s_w1, s_w3, s_w5);
}

// ---------------- output epilogue ----------------
__global__ void out_act_kernel(const float* __restrict__ b_out, float* __restrict__ out) {
    int b = blockIdx.x, j = threadIdx.x;  // 256 threads
    float v = b_out[j];
#pragma unroll
    for (int sl = 0; sl < 6; sl++)
        v += g_op[((size_t)sl * BB + b) * 256 + j];
    out[(size_t)b * 256 + j] = 1.f / (1.f + expf(-v));
}

// ---------------- launch ----------------
extern "C" void kernel_launch(void* const* d_in, const int* in_sizes, int n_in,
                              void* d_out, int out_size) {
    const float* in_data      = (const float*)d_in[0];
    const float* memory       = (const float*)d_in[1];
    const float* h_prev       = (const float*)d_in[2];
    const float* c_prev       = (const float*)d_in[3];
    const float* prev_reads   = (const float*)d_in[4];
    const float* prev_weights = (const float*)d_in[5];
    const float* W_ih  = (const float*)d_in[6];
    const float* b_ih  = (const float*)d_in[7];
    const float* W_hh  = (const float*)d_in[8];
    const float* b_hh  = (const float*)d_in[9];
    const float* W_out = (const float*)d_in[10];
    const float* b_out = (const float*)d_in[11];
    const float* Wk    = (const float*)d_in[12];
    const float* bk    = (const float*)d_in[13];
    const float* Wbeta = (const float*)d_in[14];
    const float* bbeta = (const float*)d_in[15];
    const float* Wg    = (const float*)d_in[16];
    const float* bg    = (const float*)d_in[17];
    const float* Ws    = (const float*)d_in[18];
    const float* bs    = (const float*)d_in[19];
    const float* Wgam  = (const float*)d_in[20];
    const float* bgam  = (const float*)d_in[21];
    const float* We    = (const float*)d_in[22];
    const float* be    = (const float*)d_in[23];
    const float* Wa    = (const float*)d_in[24];
    const float* ba    = (const float*)d_in[25];
    float* out = (float*)d_out;

    float* gp; cudaGetSymbolAddress((void**)&gp, g_gp);
    float* pp; cudaGetSymbolAddress((void**)&pp, g_pp);
    float* op; cudaGetSymbolAddress((void**)&op, g_op);
    float* gx; cudaGetSymbolAddress((void**)&gx, g_x);
    float* gc; cudaGetSymbolAddress((void**)&gc, g_c);
    float* ghr; cudaGetSymbolAddress((void**)&ghr, g_hr);
    float* gWstk; cudaGetSymbolAddress((void**)&gWstk, g_Wstk);

    cudaFuncSetAttribute(mega_pass, cudaFuncAttributeMaxDynamicSharedMemorySize, MEGA_SMEM);

    // 1. pack x + stacked head weights
    pack_all_kernel<<<(BB * 512 + PR * 512 + 255) / 256, 256>>>(
        in_data, prev_reads, Wk, We, Wa, Ws, Wbeta, Wg, Wgam);

    // 2. LSTM gates (both GEMMs in one launch, 8 split-K slots) + activation
    gemm_gates<<<dim3(32, 2, 8), 256>>>(gx, W_ih, h_prev, W_hh, gp);
    lstm_act_kernel<<<(BB * 128 + 255) / 256, 256>>>(b_ih, b_hh, c_prev);

    // 3. head-param GEMM (4 split-K slots) + activations
    gemm_tn<<<dim3(25, 2, 4), 256>>>(gc, gWstk, pp, PR, 512, 128, 0);
    param_act_kernel<<<dim3(8, BB), 64>>>(bk, be, ba, bs, bbeta, bg, bgam);

    // 4. all 5 memory passes in ONE kernel (fused low-barrier phase B)
    mega_pass<<<BB, 1024, MEGA_SMEM>>>(memory, prev_weights);

    // 5. output layer
    gemm_tn<<<dim3(4, 2, 6), 256>>>(ghr, W_out, op, 256, 768, 128, 0);
    out_act_kernel<<<BB, 256>>>(b_out, out);
}